// round 14
// baseline (speedup 1.0000x reference)
#include <cuda_runtime.h>

#define H_    16
#define DM    1024
#define DK    64
#define BATCH 2
#define SEQ   2048
#define NROW  (BATCH*SEQ)   // 4096
#define NREL  65
#define LOG2E 1.4426950408889634f
#define SCALE_L2 (0.125f*LOG2E)
#define FIXMAX 16.0f        // fixed softmax shift (log2 domain)

// Scratch (device globals: allocation-free scratch per harness rules)
__device__ float g_q[(size_t)BATCH*H_*SEQ*DK];     // natural [bh][s][d]
__device__ float g_k[(size_t)BATCH*H_*SEQ*DK];     // d-axis pair-interleaved
__device__ float g_vt[(size_t)BATCH*H_*DK*SEQ];    // [bh][d][s], s pair-interleaved
__device__ float g_att[(size_t)NROW*DM];           // d-axis pair-interleaved
__device__ float g_rb[NREL];                       // LOG2E*bias - FIXMAX
__device__ unsigned char g_m8[(size_t)BATCH*SEQ*SEQ];  // mask, k pair-interleaved bytes
// tf32-pre-rounded copies, k-axis pair-interleaved for LDS.64 fragments
__device__ float g_cq[(size_t)NROW*DM];
__device__ float g_ck[(size_t)NROW*DM];
__device__ float g_cv[(size_t)NROW*DM];
__device__ float g_cwq[(size_t)DM*DM];
__device__ float g_cwk[(size_t)DM*DM];
__device__ float g_cwv[(size_t)DM*DM];
__device__ float g_cwo[(size_t)DM*DM];

// pair-interleave within 8-groups: true offset o stored at pos 2*(o&3)+(o>>2);
// LDS.64 at pos 2t then yields true (t, t+4) = one mma fragment pair.
__device__ __forceinline__ int ilv8(int o){ return ((o&3)<<1) | (o>>2); }

// ---------------------------------------------------------------------------
// helpers
// ---------------------------------------------------------------------------
__device__ __forceinline__ unsigned f2tf(float x){
    unsigned r; asm("cvt.rna.tf32.f32 %0, %1;" : "=r"(r) : "f"(x)); return r;
}
__device__ __forceinline__ void mma8(float d[4],
    unsigned a0,unsigned a1,unsigned a2,unsigned a3, unsigned b0,unsigned b1){
    asm volatile("mma.sync.aligned.m16n8k8.row.col.f32.tf32.tf32.f32 "
        "{%0,%1,%2,%3}, {%4,%5,%6,%7}, {%8,%9}, {%0,%1,%2,%3};"
        : "+f"(d[0]),"+f"(d[1]),"+f"(d[2]),"+f"(d[3])
        : "r"(a0),"r"(a1),"r"(a2),"r"(a3),"r"(b0),"r"(b1));
}
__device__ __forceinline__ void cp16(void* sp, const void* gp){
    unsigned s = (unsigned)__cvta_generic_to_shared(sp);
    asm volatile("cp.async.cg.shared.global [%0], [%1], 16;" :: "r"(s), "l"(gp));
}
#define CP_COMMIT() asm volatile("cp.async.commit_group;")
#define CP_WAIT0()  asm volatile("cp.async.wait_group 0;")

// exp2 on the fma/alu pipes (MUFU is only 0.5/cyc/SM on sm_103a)
__device__ __forceinline__ float fexp2(float y){
    y = fmaxf(y, -126.f);
    float z = y + 12582912.f;
    int   e = __float_as_int(z) - 0x4B400000;
    float f = y - (z - 12582912.f);
    float p =             1.3333558146e-3f;
    p = fmaf(p, f, 9.6181291918e-3f);
    p = fmaf(p, f, 5.5504108664e-2f);
    p = fmaf(p, f, 2.4022650695e-1f);
    p = fmaf(p, f, 6.9314718056e-1f);
    p = fmaf(p, f, 1.0f);
    return __int_as_float(__float_as_int(p) + (e << 23));
}

// ---------------------------------------------------------------------------
// prepass: tf32-round + k-axis pair-interleave (z selects array)
// ---------------------------------------------------------------------------
__global__ void cvt_prepass(const float* __restrict__ q, const float* __restrict__ k,
                            const float* __restrict__ v, const float* __restrict__ wq,
                            const float* __restrict__ wk, const float* __restrict__ wv,
                            const float* __restrict__ wo)
{
    int z = blockIdx.z;
    const float4* src; float* dst; int n4;
    switch (z) {
        case 0: src=(const float4*)q;  dst=g_cq;  n4=NROW*DM/4; break;
        case 1: src=(const float4*)k;  dst=g_ck;  n4=NROW*DM/4; break;
        case 2: src=(const float4*)v;  dst=g_cv;  n4=NROW*DM/4; break;
        case 3: src=(const float4*)wq; dst=g_cwq; n4=DM*DM/4;   break;
        case 4: src=(const float4*)wk; dst=g_cwk; n4=DM*DM/4;   break;
        case 5: src=(const float4*)wv; dst=g_cwv; n4=DM*DM/4;   break;
        default:src=(const float4*)wo; dst=g_cwo; n4=DM*DM/4;   break;
    }
    for (int i = blockIdx.x*blockDim.x + threadIdx.x; i < n4; i += gridDim.x*blockDim.x){
        float4 a = src[i];
        int par  = (i & 1);                       // true offsets 0-3 (even) / 4-7 (odd)
        size_t fb = ((size_t)i << 2) & ~7ull;     // 8-aligned flat base
        dst[fb + par + 0] = __uint_as_float(f2tf(a.x));
        dst[fb + par + 2] = __uint_as_float(f2tf(a.y));
        dst[fb + par + 4] = __uint_as_float(f2tf(a.z));
        dst[fb + par + 6] = __uint_as_float(f2tf(a.w));
    }
}

// ---------------------------------------------------------------------------
// mask prepass: int32 -> uint8, k-axis pair-interleaved (uchar2 = keys t,t+4)
// ---------------------------------------------------------------------------
__global__ void mask_prepass(const int* __restrict__ mask)
{
    size_t n4 = (size_t)BATCH*SEQ*SEQ/4;
    for (size_t i = blockIdx.x*blockDim.x + threadIdx.x; i < n4;
         i += (size_t)gridDim.x*blockDim.x){
        int4 m = ((const int4*)mask)[i];
        size_t fb = (i << 2) & ~7ull;
        int par = (int)(i & 1);
        g_m8[fb + par + 0] = (unsigned char)(m.x != 0);
        g_m8[fb + par + 2] = (unsigned char)(m.y != 0);
        g_m8[fb + par + 4] = (unsigned char)(m.z != 0);
        g_m8[fb + par + 6] = (unsigned char)(m.w != 0);
    }
}

// ---------------------------------------------------------------------------
// rel bias (log2 domain, fixed softmax shift folded in)
// ---------------------------------------------------------------------------
__global__ void relbias_kernel(const float* __restrict__ rel_emb) {
    int i = threadIdx.x;
    if (i < NREL) {
        float s = 0.f;
        #pragma unroll
        for (int d = 0; d < DK; d++) s += rel_emb[i*DK + d];
        g_rb[i] = s * LOG2E - FIXMAX;
    }
}

// ---------------------------------------------------------------------------
// GEMM core: BM=128, BN=128, BK=16, 2-stage cp.async, 256 threads,
// warps 2(m)x4(n), warp tile 64x32. smem 40960 B -> 2 CTAs/SM.
// MODE: 0 = scatter natural (g_q), 1 = scatter d-interleaved (g_k),
//       2 = scatter V-transposed into g_vt, 3 = plain row-major out.
// ---------------------------------------------------------------------------
#define GBM 128
#define GBN 128
#define GBK 16
#define GPAD 20
#define GNT  (DM/GBK)

template<int MODE>
__device__ __forceinline__ void gemm_core(const float* __restrict__ X,
    const float* __restrict__ W, const float* __restrict__ bias,
    float* __restrict__ dst)
{
    extern __shared__ unsigned gsm[];
    unsigned* As = gsm;                    // [2][128][GPAD]
    unsigned* Bs = gsm + 2*GBM*GPAD;       // [2][128][GPAD]

    int tid=threadIdx.x, lane=tid&31, w=tid>>5;
    int gid=lane>>2, tig=lane&3;
    int wm=w>>2, wn=w&3;                   // 2 x 4 warp grid
    int m0=blockIdx.y*GBM, n0=blockIdx.x*GBN;

    int lr=tid>>2, lc=(tid&3)*4;           // 4 threads per 16-float row
    const float* xrow = X + (size_t)(m0+lr)*DM + lc;
    const float* wrow = W + (size_t)(n0+lr)*DM + lc;

    auto issue = [&](int t, int buf){
        int k0 = t*GBK;
        unsigned* Ab = As + buf*GBM*GPAD;
        unsigned* Bb = Bs + buf*GBN*GPAD;
        cp16(&Ab[lr*GPAD + lc],      xrow + k0);
        cp16(&Ab[(lr+64)*GPAD + lc], xrow + (size_t)64*DM + k0);
        cp16(&Bb[lr*GPAD + lc],      wrow + k0);
        cp16(&Bb[(lr+64)*GPAD + lc], wrow + (size_t)64*DM + k0);
        CP_COMMIT();
    };

    issue(0, 0);

    float acc[4][4][4]={};
    #pragma unroll 1
    for (int t=0;t<GNT;t++){
        CP_WAIT0();
        __syncthreads();
        if (t+1 < GNT) issue(t+1, (t+1)&1);

        unsigned* Ab = As + (t&1)*GBM*GPAD;
        unsigned* Bb = Bs + (t&1)*GBN*GPAD;
        #pragma unroll
        for (int kk=0;kk<2;kk++){
            int kc=kk*8 + 2*tig;
            unsigned af[4][4], bf[4][2];
            #pragma unroll
            for (int mi=0;mi<4;mi++){
                int r=wm*64+mi*16+gid;
                uint2 a02 = *(const uint2*)&Ab[r*GPAD+kc];
                uint2 a13 = *(const uint2*)&Ab[(r+8)*GPAD+kc];
                af[mi][0]=a02.x; af[mi][1]=a13.x; af[mi][2]=a02.y; af[mi][3]=a13.y;
            }
            #pragma unroll
            for (int ni=0;ni<4;ni++){
                int r=wn*32+ni*8+gid;
                uint2 b01 = *(const uint2*)&Bb[r*GPAD+kc];
                bf[ni][0]=b01.x; bf[ni][1]=b01.y;
            }
            #pragma unroll
            for (int mi=0;mi<4;mi++)
                #pragma unroll
                for (int ni=0;ni<4;ni++)
                    mma8(acc[mi][ni], af[mi][0],af[mi][1],af[mi][2],af[mi][3],
                         bf[ni][0],bf[ni][1]);
        }
    }

    #pragma unroll
    for (int mi=0;mi<4;mi++){
        #pragma unroll
        for (int ni=0;ni<4;ni++){
            int row = m0 + wm*64 + mi*16 + gid;
            int col = n0 + wn*32 + ni*8 + 2*tig;
            float bv0 = bias[col], bv1 = bias[col+1];
            float y0 = acc[mi][ni][0]+bv0, y1 = acc[mi][ni][1]+bv1;
            float y2 = acc[mi][ni][2]+bv0, y3 = acc[mi][ni][3]+bv1;
            if (MODE==3){
                *(float2*)&dst[(size_t)row*DM + col]     = make_float2(y0,y1);
                *(float2*)&dst[(size_t)(row+8)*DM + col] = make_float2(y2,y3);
            } else {
                float r0f = __uint_as_float(f2tf(y0)), r1f = __uint_as_float(f2tf(y1));
                float r2f = __uint_as_float(f2tf(y2)), r3f = __uint_as_float(f2tf(y3));
                int hh = col >> 6, dk = col & 63;
                int b1_ = row >> 11, s1 = row & (SEQ-1);
                int r2 = row + 8;
                int b2_ = r2 >> 11, s2 = r2 & (SEQ-1);
                if (MODE==2){
                    // V: write transposed [bh][d][s-interleaved]
                    int sI1 = (s1 & ~7) | ilv8(s1 & 7);
                    int sI2 = (s2 & ~7) | ilv8(s2 & 7);
                    float* pd0 = &dst[(((size_t)b1_*H_ + hh)*DK + dk)*SEQ];
                    float* pd1 = &dst[(((size_t)b1_*H_ + hh)*DK + dk+1)*SEQ];
                    float* pe0 = &dst[(((size_t)b2_*H_ + hh)*DK + dk)*SEQ];
                    float* pe1 = &dst[(((size_t)b2_*H_ + hh)*DK + dk+1)*SEQ];
                    pd0[sI1]=r0f; pd1[sI1]=r1f; pe0[sI2]=r2f; pe1[sI2]=r3f;
                } else {
                    float* p1 = &dst[(((size_t)b1_*H_ + hh)*SEQ + s1)*DK];
                    float* p2 = &dst[(((size_t)b2_*H_ + hh)*SEQ + s2)*DK];
                    if (MODE==1){
                        int g = dk & ~7, o = dk & 7;
                        int c0 = g | ilv8(o), c1 = g | ilv8(o+1);
                        p1[c0]=r0f; p1[c1]=r1f; p2[c0]=r2f; p2[c1]=r3f;
                    } else {
                        *(float2*)&p1[dk] = make_float2(r0f, r1f);
                        *(float2*)&p2[dk] = make_float2(r2f, r3f);
                    }
                }
            }
        }
    }
}

__global__ void __launch_bounds__(256, 2) gemm_qkv_kernel(
    const float* __restrict__ bq, const float* __restrict__ bk, const float* __restrict__ bv)
{
    int m = blockIdx.z;
    if (m==0)      gemm_core<0>(g_cq, g_cwq, bq, g_q);
    else if (m==1) gemm_core<1>(g_ck, g_cwk, bk, g_k);    // K: d-interleaved
    else           gemm_core<2>(g_cv, g_cwv, bv, g_vt);   // V: transposed
}

__global__ void __launch_bounds__(256, 2) gemm_out_kernel(
    const float* __restrict__ bo, float* __restrict__ out)
{
    gemm_core<3>(g_att, g_cwo, bo, out);
}

// ---------------------------------------------------------------------------
// Flash attention (R11 measured-best core): fixed-max softmax + shfl-free PV
// via store-side key permutation; conflict-free LDS; 2 CTAs/SM.
// ---------------------------------------------------------------------------
#define APAD 72

__global__ void __launch_bounds__(256, 2) attn_kernel()
{
    extern __shared__ unsigned sm_[];
    unsigned* KV = sm_;                    // [2 stages][K(64*APAD) V(64*APAD)]
    unsigned* Qf = sm_ + 4*64*APAD;        // [8 warps][8j][32 lanes][4] = 8192
    float* Qstage = (float*)sm_;           // overlay [128][APAD] over stage 0
    float* s_rb = (float*)(Qf + 8192);     // 72

    int tid=threadIdx.x, lane=tid&31, w=tid>>5;
    int gid=lane>>2, tig=lane&3;
    int bh=blockIdx.y, b=bh>>4, h=bh&15;
    int q0=blockIdx.x<<7;

    if (tid < NREL) s_rb[tid] = g_rb[tid];

    const float* kbase  = g_k  + (size_t)bh*SEQ*DK;
    const float* vtbase = g_vt + (size_t)bh*DK*SEQ;

    // stage Q, repack per-warp fragments into Qf[j][lane][4] (LDS.128 reload)
    {
        const float* qp = g_q + ((size_t)bh*SEQ + q0)*DK;
        #pragma unroll
        for (int i=0;i<8;i++){
            int idx=tid+i*256, r=idx>>4, c=(idx&15)*4;
            cp16(&Qstage[r*APAD+c], qp + (size_t)r*DK + c);
        }
        CP_COMMIT();
        CP_WAIT0();
        __syncthreads();
        int r0 = w*16 + gid;
        unsigned* Qu = (unsigned*)Qstage;
        unsigned* qfw = Qf + w*1024;
        #pragma unroll
        for (int j=0;j<8;j++){
            qfw[j*128 + lane*4 + 0] = Qu[r0*APAD + 8*j+tig];
            qfw[j*128 + lane*4 + 1] = Qu[(r0+8)*APAD + 8*j+tig];
            qfw[j*128 + lane*4 + 2] = Qu[r0*APAD + 8*j+tig+4];
            qfw[j*128 + lane*4 + 3] = Qu[(r0+8)*APAD + 8*j+tig+4];
        }
        __syncthreads();   // all warps done reading Qstage
    }
    int r0 = w*16 + gid;

    auto issue_kv = [&](int kt, int st){
        const float* kp = kbase  + (size_t)(kt<<6)*DK;   // K rows = keys (d interleaved)
        const float* vp = vtbase + (kt<<6);              // Vt rows = d (s interleaved)
        unsigned* Kst = KV + st*2*64*APAD;
        unsigned* Vst = Kst + 64*APAD;
        #pragma unroll
        for (int i=0;i<4;i++){
            int idx=tid+i*256, r=idx>>4, c=(idx&15)*4;
            int rs = (r & ~7) | ilv8(r & 7);             // key row r -> slot ilv8
            cp16(&Kst[rs*APAD+c], kp + (size_t)r*DK + c);
            cp16(&Vst[r*APAD+c],  vp + (size_t)r*SEQ + c);
        }
        CP_COMMIT();
    };
    issue_kv(0, 0);

    float oacc[8][4]={};
    float l0=0.f, l1=0.f;        // per-lane partial sums; reduced once at end
    int qg0 = q0 + r0;
    const unsigned char* mrow0 = g_m8 + (size_t)(b*SEQ + qg0)*SEQ;
    const unsigned char* mrow1 = mrow0 + (size_t)8*SEQ;
    float rb_lo = s_rb[0];   // rel <= -32 (FIXMAX folded in)
    float rb_hi = s_rb[64];  // rel >= 32
    const unsigned* qfw = Qf + w*1024 + lane*4;

    #pragma unroll 1
    for (int kt=0; kt<SEQ/64; kt++){
        int k0 = kt<<6;
        CP_WAIT0();
        __syncthreads();
        if (kt+1 < SEQ/64) issue_kv(kt+1, (kt+1)&1);

        unsigned* Kst = KV + (kt&1)*2*64*APAD;
        unsigned* Vst = Kst + 64*APAD;

        // S = Q @ K^T : conflict-free loads; slots hold permuted keys, so
        // acc regs hold keys (tig, tig+4) = PV A-fragment layout.
        float sacc[8][4]={};
        #pragma unroll
        for (int j=0;j<8;j++){
            uint4 qa = *(const uint4*)&qfw[j*128];
            #pragma unroll
            for (int nt=0;nt<8;nt++){
                uint2 kk2 = *(const uint2*)&Kst[(nt*8+gid)*APAD + 8*j + 2*tig];
                mma8(sacc[nt], qa.x,qa.y,qa.z,qa.w, kk2.x,kk2.y);
            }
        }

        // scale + bias(-FIXMAX) + mask (uchar2 = keys tig, tig+4), direct exp2
        // reg map: [0]=(q=qg0,key=ca) [1]=(qg0,cb=ca+4) [2]=(qg0+8,ca) [3]=(qg0+8,cb)
        int dlo = qg0 - (k0+63);
        int dhi = qg0 + 15 - k0;
        if (dlo >= 32 || dhi <= -32) {
            float bc = (dlo >= 32) ? rb_hi : rb_lo;
            #pragma unroll
            for (int nt=0;nt<8;nt++){
                int cp_ = k0 + nt*8 + 2*tig;
                uchar2 m0v = *(const uchar2*)&mrow0[cp_];
                uchar2 m1v = *(const uchar2*)&mrow1[cp_];
                sacc[nt][0] = (m0v.x==0) ? -3e9f : fmaf(sacc[nt][0],SCALE_L2,bc);
                sacc[nt][1] = (m0v.y==0) ? -3e9f : fmaf(sacc[nt][1],SCALE_L2,bc);
                sacc[nt][2] = (m1v.x==0) ? -3e9f : fmaf(sacc[nt][2],SCALE_L2,bc);
                sacc[nt][3] = (m1v.y==0) ? -3e9f : fmaf(sacc[nt][3],SCALE_L2,bc);
            }
        } else {
            #pragma unroll
            for (int nt=0;nt<8;nt++){
                int cp_ = k0 + nt*8 + 2*tig;
                uchar2 m0v = *(const uchar2*)&mrow0[cp_];
                uchar2 m1v = *(const uchar2*)&mrow1[cp_];
                int ca = k0 + nt*8 + tig;
                int raa = qg0 - ca;
                float b00=s_rb[min(max(raa  ,-32),32)+32];
                float b01=s_rb[min(max(raa-4,-32),32)+32];
                float b10=s_rb[min(max(raa+8,-32),32)+32];
                float b11=s_rb[min(max(raa+4,-32),32)+32];
                sacc[nt][0] = (m0v.x==0) ? -3e9f : fmaf(sacc[nt][0],SCALE_L2,b00);
                sacc[nt][1] = (m0v.y==0) ? -3e9f : fmaf(sacc[nt][1],SCALE_L2,b01);
                sacc[nt][2] = (m1v.x==0) ? -3e9f : fmaf(sacc[nt][2],SCALE_L2,b10);
                sacc[nt][3] = (m1v.y==0) ? -3e9f : fmaf(sacc[nt][3],SCALE_L2,b11);
            }
        }
        unsigned (*pu)[4] = (unsigned(*)[4])sacc;
        #pragma unroll
        for (int nt=0;nt<8;nt++){
            float p0=fexp2(sacc[nt][0]);
            float p1=fexp2(sacc[nt][1]);
            float p2=fexp2(sacc[nt][2]);
            float p3=fexp2(sacc[nt][3]);
            l0 += p0+p1; l1 += p2+p3;
            pu[nt][0]=f2tf(p0); pu[nt][1]=f2tf(p1); pu[nt][2]=f2tf(p2); pu[nt][3]=f2tf(p3);
        }

        // O += P @ V : A-frag = renamed S regs (pu[j][0],pu[j][2],pu[j][1],pu[j][3])
        #pragma unroll
        for (int j=0;j<8;j++){
            unsigned a0=pu[j][0], a1=pu[j][2], a2=pu[j][1], a3=pu[j][3];
            #pragma unroll
            for (int nt=0;nt<8;nt++){
                uint2 vv2 = *(const uint2*)&Vst[(nt*8+gid)*APAD + 8*j + 2*tig];
                mma8(oacc[nt], a0,a1,a2,a3, vv2.x,vv2.y);
            }
        }
    }

    // one final row-sum reduce (4-lane groups), then normalize + write
    l0 += __shfl_xor_sync(0xffffffffu,l0,1);
    l0 += __shfl_xor_sync(0xffffffffu,l0,2);
    l1 += __shfl_xor_sync(0xffffffffu,l1,1);
    l1 += __shfl_xor_sync(0xffffffffu,l1,2);
    float il0=1.f/l0, il1=1.f/l1;
    float* op = g_att + ((size_t)b*SEQ + qg0)*DM + h*64;
    #pragma unroll
    for (int nt=0;nt<8;nt++){
        int d = nt*8 + 2*tig;
        int g = d & ~7, o = d & 7;
        int c0 = g | ilv8(o), c1 = g | ilv8(o+1);
        op[c0] = __uint_as_float(f2tf(oacc[nt][0]*il0));
        op[c1] = __uint_as_float(f2tf(oacc[nt][1]*il0));
        op[(size_t)8*DM + c0] = __uint_as_float(f2tf(oacc[nt][2]*il1));
        op[(size_t)8*DM + c1] = __uint_as_float(f2tf(oacc[nt][3]*il1));
    }
}

// ---------------------------------------------------------------------------
extern "C" void kernel_launch(void* const* d_in, const int* in_sizes, int n_in,
                              void* d_out, int out_size)
{
    const float* query = (const float*)d_in[0];
    const float* key   = (const float*)d_in[1];
    const float* value = (const float*)d_in[2];
    const int*   mask  = (const int*)  d_in[3];
    const float* Wq    = (const float*)d_in[4];
    const float* bq    = (const float*)d_in[5];
    const float* Wk    = (const float*)d_in[6];
    const float* bk    = (const float*)d_in[7];
    const float* Wv    = (const float*)d_in[8];
    const float* bv    = (const float*)d_in[9];
    const float* Wo    = (const float*)d_in[10];
    const float* bo    = (const float*)d_in[11];
    const float* rel   = (const float*)d_in[12];
    float* out = (float*)d_out;

    size_t gsmem = (size_t)(2*GBM*GPAD + 2*GBN*GPAD) * 4;       // 40960 B
    size_t asmem = (size_t)(4*64*APAD + 8192 + 72) * 4;         // 106784 B
    cudaFuncSetAttribute(gemm_qkv_kernel, cudaFuncAttributeMaxDynamicSharedMemorySize, (int)gsmem);
    cudaFuncSetAttribute(gemm_out_kernel, cudaFuncAttributeMaxDynamicSharedMemorySize, (int)gsmem);
    cudaFuncSetAttribute(attn_kernel, cudaFuncAttributeMaxDynamicSharedMemorySize, (int)asmem);

    relbias_kernel<<<1, 128>>>(rel);
    cvt_prepass<<<dim3(1024,1,7), 256>>>(query, key, value, Wq, Wk, Wv, Wo);
    mask_prepass<<<2048, 256>>>(mask);

    dim3 pg(DM/GBN, NROW/GBM, 3);   // (8, 32, 3)
    gemm_qkv_kernel<<<pg, 256, gsmem>>>(bq, bk, bv);

    attn_kernel<<<dim3(SEQ/128, BATCH*H_), 256, asmem>>>();

    gemm_out_kernel<<<dim3(DM/GBN, NROW/GBM), 256, gsmem>>>(bo, out);
}

// round 15
// speedup vs baseline: 1.0543x; 1.0543x over previous
#include <cuda_runtime.h>

#define H_    16
#define DM    1024
#define DK    64
#define BATCH 2
#define SEQ   2048
#define NROW  (BATCH*SEQ)   // 4096
#define NREL  65
#define LOG2E 1.4426950408889634f
#define SCALE_L2 (0.125f*LOG2E)
#define FIXMAX 16.0f        // fixed softmax shift (log2 domain)

// Scratch (device globals: allocation-free scratch per harness rules)
__device__ float g_q[(size_t)BATCH*H_*SEQ*DK];     // natural [bh][s][d]
__device__ float g_k[(size_t)BATCH*H_*SEQ*DK];     // d-axis pair-interleaved
__device__ float g_vt[(size_t)BATCH*H_*DK*SEQ];    // [bh][d][s], s pair-interleaved
__device__ float g_att[(size_t)NROW*DM];           // d-axis pair-interleaved
__device__ float g_rb[NREL];                       // LOG2E*bias - FIXMAX
__device__ unsigned char g_m8[(size_t)BATCH*SEQ*SEQ];  // mask, k pair-interleaved bytes
// tf32-pre-rounded copies, k-axis pair-interleaved for LDS.64 fragments
__device__ float g_cq[(size_t)NROW*DM];
__device__ float g_ck[(size_t)NROW*DM];
__device__ float g_cv[(size_t)NROW*DM];
__device__ float g_cwq[(size_t)DM*DM];
__device__ float g_cwk[(size_t)DM*DM];
__device__ float g_cwv[(size_t)DM*DM];
__device__ float g_cwo[(size_t)DM*DM];

// pair-interleave within 8-groups: true offset o stored at pos 2*(o&3)+(o>>2);
// LDS.64 at pos 2t then yields true (t, t+4) = one mma fragment pair.
__device__ __forceinline__ int ilv8(int o){ return ((o&3)<<1) | (o>>2); }

// ---------------------------------------------------------------------------
// helpers
// ---------------------------------------------------------------------------
__device__ __forceinline__ unsigned f2tf(float x){
    unsigned r; asm("cvt.rna.tf32.f32 %0, %1;" : "=r"(r) : "f"(x)); return r;
}
__device__ __forceinline__ void mma8(float d[4],
    unsigned a0,unsigned a1,unsigned a2,unsigned a3, unsigned b0,unsigned b1){
    asm volatile("mma.sync.aligned.m16n8k8.row.col.f32.tf32.tf32.f32 "
        "{%0,%1,%2,%3}, {%4,%5,%6,%7}, {%8,%9}, {%0,%1,%2,%3};"
        : "+f"(d[0]),"+f"(d[1]),"+f"(d[2]),"+f"(d[3])
        : "r"(a0),"r"(a1),"r"(a2),"r"(a3),"r"(b0),"r"(b1));
}
__device__ __forceinline__ void cp16(void* sp, const void* gp){
    unsigned s = (unsigned)__cvta_generic_to_shared(sp);
    asm volatile("cp.async.ca.shared.global [%0], [%1], 16;" :: "r"(s), "l"(gp));
}
#define CP_COMMIT() asm volatile("cp.async.commit_group;")
#define CP_WAIT0()  asm volatile("cp.async.wait_group 0;")
#define CP_WAIT1()  asm volatile("cp.async.wait_group 1;")

// exp2 on the fma/alu pipes (MUFU is only 0.5/cyc/SM on sm_103a)
__device__ __forceinline__ float fexp2(float y){
    y = fmaxf(y, -126.f);
    float z = y + 12582912.f;
    int   e = __float_as_int(z) - 0x4B400000;
    float f = y - (z - 12582912.f);
    float p =             1.3333558146e-3f;
    p = fmaf(p, f, 9.6181291918e-3f);
    p = fmaf(p, f, 5.5504108664e-2f);
    p = fmaf(p, f, 2.4022650695e-1f);
    p = fmaf(p, f, 6.9314718056e-1f);
    p = fmaf(p, f, 1.0f);
    return __int_as_float(__float_as_int(p) + (e << 23));
}

// ---------------------------------------------------------------------------
// prepass: tf32-round + k-axis pair-interleave (z selects array)
// ---------------------------------------------------------------------------
__global__ void cvt_prepass(const float* __restrict__ q, const float* __restrict__ k,
                            const float* __restrict__ v, const float* __restrict__ wq,
                            const float* __restrict__ wk, const float* __restrict__ wv,
                            const float* __restrict__ wo)
{
    int z = blockIdx.z;
    const float4* src; float* dst; int n4;
    switch (z) {
        case 0: src=(const float4*)q;  dst=g_cq;  n4=NROW*DM/4; break;
        case 1: src=(const float4*)k;  dst=g_ck;  n4=NROW*DM/4; break;
        case 2: src=(const float4*)v;  dst=g_cv;  n4=NROW*DM/4; break;
        case 3: src=(const float4*)wq; dst=g_cwq; n4=DM*DM/4;   break;
        case 4: src=(const float4*)wk; dst=g_cwk; n4=DM*DM/4;   break;
        case 5: src=(const float4*)wv; dst=g_cwv; n4=DM*DM/4;   break;
        default:src=(const float4*)wo; dst=g_cwo; n4=DM*DM/4;   break;
    }
    for (int i = blockIdx.x*blockDim.x + threadIdx.x; i < n4; i += gridDim.x*blockDim.x){
        float4 a = src[i];
        int par  = (i & 1);                       // true offsets 0-3 (even) / 4-7 (odd)
        size_t fb = ((size_t)i << 2) & ~7ull;     // 8-aligned flat base
        dst[fb + par + 0] = __uint_as_float(f2tf(a.x));
        dst[fb + par + 2] = __uint_as_float(f2tf(a.y));
        dst[fb + par + 4] = __uint_as_float(f2tf(a.z));
        dst[fb + par + 6] = __uint_as_float(f2tf(a.w));
    }
}

// ---------------------------------------------------------------------------
// mask prepass: int32 -> uint8, k-axis pair-interleaved (uchar2 = keys t,t+4)
// ---------------------------------------------------------------------------
__global__ void mask_prepass(const int* __restrict__ mask)
{
    size_t n4 = (size_t)BATCH*SEQ*SEQ/4;
    for (size_t i = blockIdx.x*blockDim.x + threadIdx.x; i < n4;
         i += (size_t)gridDim.x*blockDim.x){
        int4 m = ((const int4*)mask)[i];
        size_t fb = (i << 2) & ~7ull;
        int par = (int)(i & 1);
        g_m8[fb + par + 0] = (unsigned char)(m.x != 0);
        g_m8[fb + par + 2] = (unsigned char)(m.y != 0);
        g_m8[fb + par + 4] = (unsigned char)(m.z != 0);
        g_m8[fb + par + 6] = (unsigned char)(m.w != 0);
    }
}

// ---------------------------------------------------------------------------
// rel bias (log2 domain, fixed softmax shift folded in)
// ---------------------------------------------------------------------------
__global__ void relbias_kernel(const float* __restrict__ rel_emb) {
    int i = threadIdx.x;
    if (i < NREL) {
        float s = 0.f;
        #pragma unroll
        for (int d = 0; d < DK; d++) s += rel_emb[i*DK + d];
        g_rb[i] = s * LOG2E - FIXMAX;
    }
}

// ---------------------------------------------------------------------------
// GEMM core: BM=128, BN=128, BK=32, 3-stage cp.async (wait_group 1),
// 256 threads, warps 2(m)x4(n), warp tile 64x32 (0.75 LDS.64 per MMA).
// MODE: 0 = scatter natural (g_q), 1 = scatter d-interleaved (g_k),
//       2 = scatter V-transposed into g_vt, 3 = plain row-major out.
// ---------------------------------------------------------------------------
#define GBM 128
#define GBN 128
#define GBK 32
#define GPAD 40
#define GNT  (DM/GBK)

template<int MODE>
__device__ __forceinline__ void gemm_core(const float* __restrict__ X,
    const float* __restrict__ W, const float* __restrict__ bias,
    float* __restrict__ dst)
{
    extern __shared__ unsigned gsm[];
    unsigned* As = gsm;                    // [3][128][GPAD]
    unsigned* Bs = gsm + 3*GBM*GPAD;       // [3][128][GPAD]

    int tid=threadIdx.x, lane=tid&31, w=tid>>5;
    int gid=lane>>2, tig=lane&3;
    int wm=w>>2, wn=w&3;                   // 2 x 4 warp grid
    int m0=blockIdx.y*GBM, n0=blockIdx.x*GBN;

    int lr=tid>>3, lc=(tid&7)*4;
    const float* xp = X + (size_t)(m0+lr)*DM + lc;
    const float* wp = W + (size_t)(n0+lr)*DM + lc;

    auto issue = [&](int t, int buf){
        int k0 = t*GBK;
        #pragma unroll
        for (int i=0;i<4;i++)
            cp16(&As[buf*GBM*GPAD + (lr+32*i)*GPAD + lc], xp + k0 + (size_t)32*i*DM);
        #pragma unroll
        for (int i=0;i<4;i++)
            cp16(&Bs[buf*GBN*GPAD + (lr+32*i)*GPAD + lc], wp + k0 + (size_t)32*i*DM);
        CP_COMMIT();
    };

    issue(0, 0);
    issue(1, 1);

    float acc[4][4][4]={};
    int buf = 0;
    #pragma unroll 1
    for (int t=0;t<GNT;t++){
        if (t < GNT-1) { CP_WAIT1(); } else { CP_WAIT0(); }
        __syncthreads();
        if (t+2 < GNT) { int nb = buf+2; if (nb>=3) nb-=3; issue(t+2, nb); }

        unsigned* Ab = As + buf*GBM*GPAD;
        unsigned* Bb = Bs + buf*GBN*GPAD;
        #pragma unroll
        for (int kk=0;kk<4;kk++){
            int kc=kk*8 + 2*tig;
            unsigned af[4][4], bf[4][2];
            #pragma unroll
            for (int mi=0;mi<4;mi++){
                int r=wm*64+mi*16+gid;
                uint2 a02 = *(const uint2*)&Ab[r*GPAD+kc];
                uint2 a13 = *(const uint2*)&Ab[(r+8)*GPAD+kc];
                af[mi][0]=a02.x; af[mi][1]=a13.x; af[mi][2]=a02.y; af[mi][3]=a13.y;
            }
            #pragma unroll
            for (int ni=0;ni<4;ni++){
                int r=wn*32+ni*8+gid;
                uint2 b01 = *(const uint2*)&Bb[r*GPAD+kc];
                bf[ni][0]=b01.x; bf[ni][1]=b01.y;
            }
            #pragma unroll
            for (int mi=0;mi<4;mi++)
                #pragma unroll
                for (int ni=0;ni<4;ni++)
                    mma8(acc[mi][ni], af[mi][0],af[mi][1],af[mi][2],af[mi][3],
                         bf[ni][0],bf[ni][1]);
        }
        buf++; if (buf>=3) buf=0;
    }

    #pragma unroll
    for (int mi=0;mi<4;mi++){
        #pragma unroll
        for (int ni=0;ni<4;ni++){
            int row = m0 + wm*64 + mi*16 + gid;
            int col = n0 + wn*32 + ni*8 + 2*tig;
            float bv0 = bias[col], bv1 = bias[col+1];
            float y0 = acc[mi][ni][0]+bv0, y1 = acc[mi][ni][1]+bv1;
            float y2 = acc[mi][ni][2]+bv0, y3 = acc[mi][ni][3]+bv1;
            if (MODE==3){
                *(float2*)&dst[(size_t)row*DM + col]     = make_float2(y0,y1);
                *(float2*)&dst[(size_t)(row+8)*DM + col] = make_float2(y2,y3);
            } else {
                float r0f = __uint_as_float(f2tf(y0)), r1f = __uint_as_float(f2tf(y1));
                float r2f = __uint_as_float(f2tf(y2)), r3f = __uint_as_float(f2tf(y3));
                int hh = col >> 6, dk = col & 63;
                int b1_ = row >> 11, s1 = row & (SEQ-1);
                int r2 = row + 8;
                int b2_ = r2 >> 11, s2 = r2 & (SEQ-1);
                if (MODE==2){
                    // V: write transposed [bh][d][s-interleaved]
                    int sI1 = (s1 & ~7) | ilv8(s1 & 7);
                    int sI2 = (s2 & ~7) | ilv8(s2 & 7);
                    float* pd0 = &dst[(((size_t)b1_*H_ + hh)*DK + dk)*SEQ];
                    float* pd1 = &dst[(((size_t)b1_*H_ + hh)*DK + dk+1)*SEQ];
                    float* pe0 = &dst[(((size_t)b2_*H_ + hh)*DK + dk)*SEQ];
                    float* pe1 = &dst[(((size_t)b2_*H_ + hh)*DK + dk+1)*SEQ];
                    pd0[sI1]=r0f; pd1[sI1]=r1f; pe0[sI2]=r2f; pe1[sI2]=r3f;
                } else {
                    float* p1 = &dst[(((size_t)b1_*H_ + hh)*SEQ + s1)*DK];
                    float* p2 = &dst[(((size_t)b2_*H_ + hh)*SEQ + s2)*DK];
                    if (MODE==1){
                        int g = dk & ~7, o = dk & 7;
                        int c0 = g | ilv8(o), c1 = g | ilv8(o+1);
                        p1[c0]=r0f; p1[c1]=r1f; p2[c0]=r2f; p2[c1]=r3f;
                    } else {
                        *(float2*)&p1[dk] = make_float2(r0f, r1f);
                        *(float2*)&p2[dk] = make_float2(r2f, r3f);
                    }
                }
            }
        }
    }
}

__global__ void __launch_bounds__(256) gemm_qkv_kernel(
    const float* __restrict__ bq, const float* __restrict__ bk, const float* __restrict__ bv)
{
    int m = blockIdx.z;
    if (m==0)      gemm_core<0>(g_cq, g_cwq, bq, g_q);
    else if (m==1) gemm_core<1>(g_ck, g_cwk, bk, g_k);    // K: d-interleaved
    else           gemm_core<2>(g_cv, g_cwv, bv, g_vt);   // V: transposed
}

__global__ void __launch_bounds__(256) gemm_out_kernel(
    const float* __restrict__ bo, float* __restrict__ out)
{
    gemm_core<3>(g_att, g_cwo, bo, out);
}

// ---------------------------------------------------------------------------
// Flash attention (R11 measured-best core): fixed-max softmax + shfl-free PV
// via store-side key permutation; conflict-free LDS; 2 CTAs/SM.
// ---------------------------------------------------------------------------
#define APAD 72

__global__ void __launch_bounds__(256, 2) attn_kernel()
{
    extern __shared__ unsigned sm_[];
    unsigned* KV = sm_;                    // [2 stages][K(64*APAD) V(64*APAD)]
    unsigned* Qf = sm_ + 4*64*APAD;        // [8 warps][8j][32 lanes][4] = 8192
    float* Qstage = (float*)sm_;           // overlay [128][APAD] over stage 0
    float* s_rb = (float*)(Qf + 8192);     // 72

    int tid=threadIdx.x, lane=tid&31, w=tid>>5;
    int gid=lane>>2, tig=lane&3;
    int bh=blockIdx.y, b=bh>>4, h=bh&15;
    int q0=blockIdx.x<<7;

    if (tid < NREL) s_rb[tid] = g_rb[tid];

    const float* kbase  = g_k  + (size_t)bh*SEQ*DK;
    const float* vtbase = g_vt + (size_t)bh*DK*SEQ;

    // stage Q, repack per-warp fragments into Qf[j][lane][4] (LDS.128 reload)
    {
        const float* qp = g_q + ((size_t)bh*SEQ + q0)*DK;
        #pragma unroll
        for (int i=0;i<8;i++){
            int idx=tid+i*256, r=idx>>4, c=(idx&15)*4;
            cp16(&Qstage[r*APAD+c], qp + (size_t)r*DK + c);
        }
        CP_COMMIT();
        CP_WAIT0();
        __syncthreads();
        int r0 = w*16 + gid;
        unsigned* Qu = (unsigned*)Qstage;
        unsigned* qfw = Qf + w*1024;
        #pragma unroll
        for (int j=0;j<8;j++){
            qfw[j*128 + lane*4 + 0] = Qu[r0*APAD + 8*j+tig];
            qfw[j*128 + lane*4 + 1] = Qu[(r0+8)*APAD + 8*j+tig];
            qfw[j*128 + lane*4 + 2] = Qu[r0*APAD + 8*j+tig+4];
            qfw[j*128 + lane*4 + 3] = Qu[(r0+8)*APAD + 8*j+tig+4];
        }
        __syncthreads();   // all warps done reading Qstage
    }
    int r0 = w*16 + gid;

    auto issue_kv = [&](int kt, int st){
        const float* kp = kbase  + (size_t)(kt<<6)*DK;   // K rows = keys (d interleaved)
        const float* vp = vtbase + (kt<<6);              // Vt rows = d (s interleaved)
        unsigned* Kst = KV + st*2*64*APAD;
        unsigned* Vst = Kst + 64*APAD;
        #pragma unroll
        for (int i=0;i<4;i++){
            int idx=tid+i*256, r=idx>>4, c=(idx&15)*4;
            int rs = (r & ~7) | ilv8(r & 7);             // key row r -> slot ilv8
            cp16(&Kst[rs*APAD+c], kp + (size_t)r*DK + c);
            cp16(&Vst[r*APAD+c],  vp + (size_t)r*SEQ + c);
        }
        CP_COMMIT();
    };
    issue_kv(0, 0);

    float oacc[8][4]={};
    float l0=0.f, l1=0.f;        // per-lane partial sums; reduced once at end
    int qg0 = q0 + r0;
    const unsigned char* mrow0 = g_m8 + (size_t)(b*SEQ + qg0)*SEQ;
    const unsigned char* mrow1 = mrow0 + (size_t)8*SEQ;
    float rb_lo = s_rb[0];   // rel <= -32 (FIXMAX folded in)
    float rb_hi = s_rb[64];  // rel >= 32
    const unsigned* qfw = Qf + w*1024 + lane*4;

    #pragma unroll 1
    for (int kt=0; kt<SEQ/64; kt++){
        int k0 = kt<<6;
        CP_WAIT0();
        __syncthreads();
        if (kt+1 < SEQ/64) issue_kv(kt+1, (kt+1)&1);

        unsigned* Kst = KV + (kt&1)*2*64*APAD;
        unsigned* Vst = Kst + 64*APAD;

        // S = Q @ K^T : conflict-free loads; slots hold permuted keys, so
        // acc regs hold keys (tig, tig+4) = PV A-fragment layout.
        float sacc[8][4]={};
        #pragma unroll
        for (int j=0;j<8;j++){
            uint4 qa = *(const uint4*)&qfw[j*128];
            #pragma unroll
            for (int nt=0;nt<8;nt++){
                uint2 kk2 = *(const uint2*)&Kst[(nt*8+gid)*APAD + 8*j + 2*tig];
                mma8(sacc[nt], qa.x,qa.y,qa.z,qa.w, kk2.x,kk2.y);
            }
        }

        // scale + bias(-FIXMAX) + mask (uchar2 = keys tig, tig+4), direct exp2
        // reg map: [0]=(q=qg0,key=ca) [1]=(qg0,cb=ca+4) [2]=(qg0+8,ca) [3]=(qg0+8,cb)
        int dlo = qg0 - (k0+63);
        int dhi = qg0 + 15 - k0;
        if (dlo >= 32 || dhi <= -32) {
            float bc = (dlo >= 32) ? rb_hi : rb_lo;
            #pragma unroll
            for (int nt=0;nt<8;nt++){
                int cp_ = k0 + nt*8 + 2*tig;
                uchar2 m0v = *(const uchar2*)&mrow0[cp_];
                uchar2 m1v = *(const uchar2*)&mrow1[cp_];
                sacc[nt][0] = (m0v.x==0) ? -3e9f : fmaf(sacc[nt][0],SCALE_L2,bc);
                sacc[nt][1] = (m0v.y==0) ? -3e9f : fmaf(sacc[nt][1],SCALE_L2,bc);
                sacc[nt][2] = (m1v.x==0) ? -3e9f : fmaf(sacc[nt][2],SCALE_L2,bc);
                sacc[nt][3] = (m1v.y==0) ? -3e9f : fmaf(sacc[nt][3],SCALE_L2,bc);
            }
        } else {
            #pragma unroll
            for (int nt=0;nt<8;nt++){
                int cp_ = k0 + nt*8 + 2*tig;
                uchar2 m0v = *(const uchar2*)&mrow0[cp_];
                uchar2 m1v = *(const uchar2*)&mrow1[cp_];
                int ca = k0 + nt*8 + tig;
                int raa = qg0 - ca;
                float b00=s_rb[min(max(raa  ,-32),32)+32];
                float b01=s_rb[min(max(raa-4,-32),32)+32];
                float b10=s_rb[min(max(raa+8,-32),32)+32];
                float b11=s_rb[min(max(raa+4,-32),32)+32];
                sacc[nt][0] = (m0v.x==0) ? -3e9f : fmaf(sacc[nt][0],SCALE_L2,b00);
                sacc[nt][1] = (m0v.y==0) ? -3e9f : fmaf(sacc[nt][1],SCALE_L2,b01);
                sacc[nt][2] = (m1v.x==0) ? -3e9f : fmaf(sacc[nt][2],SCALE_L2,b10);
                sacc[nt][3] = (m1v.y==0) ? -3e9f : fmaf(sacc[nt][3],SCALE_L2,b11);
            }
        }
        unsigned (*pu)[4] = (unsigned(*)[4])sacc;
        #pragma unroll
        for (int nt=0;nt<8;nt++){
            float p0=fexp2(sacc[nt][0]);
            float p1=fexp2(sacc[nt][1]);
            float p2=fexp2(sacc[nt][2]);
            float p3=fexp2(sacc[nt][3]);
            l0 += p0+p1; l1 += p2+p3;
            pu[nt][0]=f2tf(p0); pu[nt][1]=f2tf(p1); pu[nt][2]=f2tf(p2); pu[nt][3]=f2tf(p3);
        }

        // O += P @ V : A-frag = renamed S regs (pu[j][0],pu[j][2],pu[j][1],pu[j][3])
        #pragma unroll
        for (int j=0;j<8;j++){
            unsigned a0=pu[j][0], a1=pu[j][2], a2=pu[j][1], a3=pu[j][3];
            #pragma unroll
            for (int nt=0;nt<8;nt++){
                uint2 vv2 = *(const uint2*)&Vst[(nt*8+gid)*APAD + 8*j + 2*tig];
                mma8(oacc[nt], a0,a1,a2,a3, vv2.x,vv2.y);
            }
        }
    }

    // one final row-sum reduce (4-lane groups), then normalize + write
    l0 += __shfl_xor_sync(0xffffffffu,l0,1);
    l0 += __shfl_xor_sync(0xffffffffu,l0,2);
    l1 += __shfl_xor_sync(0xffffffffu,l1,1);
    l1 += __shfl_xor_sync(0xffffffffu,l1,2);
    float il0=1.f/l0, il1=1.f/l1;
    float* op = g_att + ((size_t)b*SEQ + qg0)*DM + h*64;
    #pragma unroll
    for (int nt=0;nt<8;nt++){
        int d = nt*8 + 2*tig;
        int g = d & ~7, o = d & 7;
        int c0 = g | ilv8(o), c1 = g | ilv8(o+1);
        op[c0] = __uint_as_float(f2tf(oacc[nt][0]*il0));
        op[c1] = __uint_as_float(f2tf(oacc[nt][1]*il0));
        op[(size_t)8*DM + c0] = __uint_as_float(f2tf(oacc[nt][2]*il1));
        op[(size_t)8*DM + c1] = __uint_as_float(f2tf(oacc[nt][3]*il1));
    }
}

// ---------------------------------------------------------------------------
extern "C" void kernel_launch(void* const* d_in, const int* in_sizes, int n_in,
                              void* d_out, int out_size)
{
    const float* query = (const float*)d_in[0];
    const float* key   = (const float*)d_in[1];
    const float* value = (const float*)d_in[2];
    const int*   mask  = (const int*)  d_in[3];
    const float* Wq    = (const float*)d_in[4];
    const float* bq    = (const float*)d_in[5];
    const float* Wk    = (const float*)d_in[6];
    const float* bk    = (const float*)d_in[7];
    const float* Wv    = (const float*)d_in[8];
    const float* bv    = (const float*)d_in[9];
    const float* Wo    = (const float*)d_in[10];
    const float* bo    = (const float*)d_in[11];
    const float* rel   = (const float*)d_in[12];
    float* out = (float*)d_out;

    size_t gsmem = (size_t)(3*GBM*GPAD + 3*GBN*GPAD) * 4;       // 122880 B
    size_t asmem = (size_t)(4*64*APAD + 8192 + 72) * 4;         // 106784 B
    cudaFuncSetAttribute(gemm_qkv_kernel, cudaFuncAttributeMaxDynamicSharedMemorySize, (int)gsmem);
    cudaFuncSetAttribute(gemm_out_kernel, cudaFuncAttributeMaxDynamicSharedMemorySize, (int)gsmem);
    cudaFuncSetAttribute(attn_kernel, cudaFuncAttributeMaxDynamicSharedMemorySize, (int)asmem);

    relbias_kernel<<<1, 128>>>(rel);
    cvt_prepass<<<dim3(1024,1,7), 256>>>(query, key, value, Wq, Wk, Wv, Wo);
    mask_prepass<<<2048, 256>>>(mask);

    dim3 pg(DM/GBN, NROW/GBM, 3);   // (8, 32, 3)
    gemm_qkv_kernel<<<pg, 256, gsmem>>>(bq, bk, bv);

    attn_kernel<<<dim3(SEQ/128, BATCH*H_), 256, asmem>>>();

    gemm_out_kernel<<<dim3(DM/GBN, NROW/GBM), 256, gsmem>>>(bo, out);
}

// round 16
// speedup vs baseline: 1.0780x; 1.0225x over previous
#include <cuda_runtime.h>

#define H_    16
#define DM    1024
#define DK    64
#define BATCH 2
#define SEQ   2048
#define NROW  (BATCH*SEQ)   // 4096
#define NREL  65
#define LOG2E 1.4426950408889634f
#define SCALE_L2 (0.125f*LOG2E)
#define FIXMAX 16.0f        // fixed softmax shift (log2 domain)

// Scratch (device globals: allocation-free scratch per harness rules)
__device__ float g_q[(size_t)BATCH*H_*SEQ*DK];     // natural [bh][s][d]
__device__ float g_k[(size_t)BATCH*H_*SEQ*DK];     // d-axis pair-interleaved
__device__ float g_vt[(size_t)BATCH*H_*DK*SEQ];    // [bh][d][s], s pair-interleaved
__device__ float g_att[(size_t)NROW*DM];           // d-axis pair-interleaved
__device__ float g_rb[NREL];                       // LOG2E*bias - FIXMAX
__device__ unsigned char g_m8[(size_t)BATCH*SEQ*SEQ];  // mask, k pair-interleaved bytes
// tf32-pre-rounded copies, k-axis pair-interleaved for LDS.64 fragments
__device__ float g_cq[(size_t)NROW*DM];
__device__ float g_ck[(size_t)NROW*DM];
__device__ float g_cv[(size_t)NROW*DM];
__device__ float g_cwq[(size_t)DM*DM];
__device__ float g_cwk[(size_t)DM*DM];
__device__ float g_cwv[(size_t)DM*DM];
__device__ float g_cwo[(size_t)DM*DM];

// pair-interleave within 8-groups: true offset o stored at pos 2*(o&3)+(o>>2);
// LDS.64 at pos 2t then yields true (t, t+4) = one mma fragment pair.
__device__ __forceinline__ int ilv8(int o){ return ((o&3)<<1) | (o>>2); }

// ---------------------------------------------------------------------------
// helpers
// ---------------------------------------------------------------------------
__device__ __forceinline__ unsigned f2tf(float x){
    unsigned r; asm("cvt.rna.tf32.f32 %0, %1;" : "=r"(r) : "f"(x)); return r;
}
__device__ __forceinline__ void mma8(float d[4],
    unsigned a0,unsigned a1,unsigned a2,unsigned a3, unsigned b0,unsigned b1){
    asm volatile("mma.sync.aligned.m16n8k8.row.col.f32.tf32.tf32.f32 "
        "{%0,%1,%2,%3}, {%4,%5,%6,%7}, {%8,%9}, {%0,%1,%2,%3};"
        : "+f"(d[0]),"+f"(d[1]),"+f"(d[2]),"+f"(d[3])
        : "r"(a0),"r"(a1),"r"(a2),"r"(a3),"r"(b0),"r"(b1));
}
__device__ __forceinline__ void cp16(void* sp, const void* gp){
    unsigned s = (unsigned)__cvta_generic_to_shared(sp);
    asm volatile("cp.async.ca.shared.global [%0], [%1], 16;" :: "r"(s), "l"(gp));
}
#define CP_COMMIT() asm volatile("cp.async.commit_group;")
#define CP_WAIT0()  asm volatile("cp.async.wait_group 0;")

// exp2 on the fma/alu pipes (MUFU is only 0.5/cyc/SM on sm_103a)
__device__ __forceinline__ float fexp2(float y){
    y = fmaxf(y, -126.f);
    float z = y + 12582912.f;
    int   e = __float_as_int(z) - 0x4B400000;
    float f = y - (z - 12582912.f);
    float p =             1.3333558146e-3f;
    p = fmaf(p, f, 9.6181291918e-3f);
    p = fmaf(p, f, 5.5504108664e-2f);
    p = fmaf(p, f, 2.4022650695e-1f);
    p = fmaf(p, f, 6.9314718056e-1f);
    p = fmaf(p, f, 1.0f);
    return __int_as_float(__float_as_int(p) + (e << 23));
}

// ---------------------------------------------------------------------------
// prepass: tf32-round + k-axis pair-interleave (z selects array)
// ---------------------------------------------------------------------------
__global__ void cvt_prepass(const float* __restrict__ q, const float* __restrict__ k,
                            const float* __restrict__ v, const float* __restrict__ wq,
                            const float* __restrict__ wk, const float* __restrict__ wv,
                            const float* __restrict__ wo)
{
    int z = blockIdx.z;
    const float4* src; float* dst; int n4;
    switch (z) {
        case 0: src=(const float4*)q;  dst=g_cq;  n4=NROW*DM/4; break;
        case 1: src=(const float4*)k;  dst=g_ck;  n4=NROW*DM/4; break;
        case 2: src=(const float4*)v;  dst=g_cv;  n4=NROW*DM/4; break;
        case 3: src=(const float4*)wq; dst=g_cwq; n4=DM*DM/4;   break;
        case 4: src=(const float4*)wk; dst=g_cwk; n4=DM*DM/4;   break;
        case 5: src=(const float4*)wv; dst=g_cwv; n4=DM*DM/4;   break;
        default:src=(const float4*)wo; dst=g_cwo; n4=DM*DM/4;   break;
    }
    for (int i = blockIdx.x*blockDim.x + threadIdx.x; i < n4; i += gridDim.x*blockDim.x){
        float4 a = src[i];
        int par  = (i & 1);                       // true offsets 0-3 (even) / 4-7 (odd)
        size_t fb = ((size_t)i << 2) & ~7ull;     // 8-aligned flat base
        dst[fb + par + 0] = __uint_as_float(f2tf(a.x));
        dst[fb + par + 2] = __uint_as_float(f2tf(a.y));
        dst[fb + par + 4] = __uint_as_float(f2tf(a.z));
        dst[fb + par + 6] = __uint_as_float(f2tf(a.w));
    }
}

// ---------------------------------------------------------------------------
// mask prepass: int32 -> uint8, k-axis pair-interleaved (uchar2 = keys t,t+4)
// ---------------------------------------------------------------------------
__global__ void mask_prepass(const int* __restrict__ mask)
{
    size_t n4 = (size_t)BATCH*SEQ*SEQ/4;
    for (size_t i = blockIdx.x*blockDim.x + threadIdx.x; i < n4;
         i += (size_t)gridDim.x*blockDim.x){
        int4 m = ((const int4*)mask)[i];
        size_t fb = (i << 2) & ~7ull;
        int par = (int)(i & 1);
        g_m8[fb + par + 0] = (unsigned char)(m.x != 0);
        g_m8[fb + par + 2] = (unsigned char)(m.y != 0);
        g_m8[fb + par + 4] = (unsigned char)(m.z != 0);
        g_m8[fb + par + 6] = (unsigned char)(m.w != 0);
    }
}

// ---------------------------------------------------------------------------
// rel bias (log2 domain, fixed softmax shift folded in)
// ---------------------------------------------------------------------------
__global__ void relbias_kernel(const float* __restrict__ rel_emb) {
    int i = threadIdx.x;
    if (i < NREL) {
        float s = 0.f;
        #pragma unroll
        for (int d = 0; d < DK; d++) s += rel_emb[i*DK + d];
        g_rb[i] = s * LOG2E - FIXMAX;
    }
}

// ---------------------------------------------------------------------------
// GEMM core: BM=128, BN=128, BK=32, 2-stage cp.async, 256 threads,
// warps 2(m)x4(n), warp tile 64x32. Fragment registers double-buffered
// across kk-steps (LDS for kk+1 issued before kk's MMAs).
// MODE: 0 = scatter natural (g_q), 1 = scatter d-interleaved (g_k),
//       2 = scatter V-transposed into g_vt, 3 = plain row-major out.
// ---------------------------------------------------------------------------
#define GBM 128
#define GBN 128
#define GBK 32
#define GPAD 40
#define GNT  (DM/GBK)

template<int MODE>
__device__ __forceinline__ void gemm_core(const float* __restrict__ X,
    const float* __restrict__ W, const float* __restrict__ bias,
    float* __restrict__ dst)
{
    extern __shared__ unsigned gsm[];
    unsigned* As = gsm;                    // [2][128][GPAD]
    unsigned* Bs = gsm + 2*GBM*GPAD;       // [2][128][GPAD]

    int tid=threadIdx.x, lane=tid&31, w=tid>>5;
    int gid=lane>>2, tig=lane&3;
    int wm=w>>2, wn=w&3;                   // 2 x 4 warp grid
    int m0=blockIdx.y*GBM, n0=blockIdx.x*GBN;

    int lr=tid>>3, lc=(tid&7)*4;
    const float* xp = X + (size_t)(m0+lr)*DM + lc;
    const float* wp = W + (size_t)(n0+lr)*DM + lc;

    auto issue = [&](int t, int buf){
        int k0 = t*GBK;
        #pragma unroll
        for (int i=0;i<4;i++)
            cp16(&As[buf*GBM*GPAD + (lr+32*i)*GPAD + lc], xp + k0 + (size_t)32*i*DM);
        #pragma unroll
        for (int i=0;i<4;i++)
            cp16(&Bs[buf*GBN*GPAD + (lr+32*i)*GPAD + lc], wp + k0 + (size_t)32*i*DM);
        CP_COMMIT();
    };

    issue(0, 0);

    float acc[4][4][4]={};
    unsigned af[2][4][4], bf[2][4][2];

    auto ldfrag = [&](unsigned* Ab, unsigned* Bb, int kk, int pb){
        int kc = kk*8 + 2*tig;
        #pragma unroll
        for (int mi=0;mi<4;mi++){
            int r=wm*64+mi*16+gid;
            uint2 a02 = *(const uint2*)&Ab[r*GPAD+kc];
            uint2 a13 = *(const uint2*)&Ab[(r+8)*GPAD+kc];
            af[pb][mi][0]=a02.x; af[pb][mi][1]=a13.x; af[pb][mi][2]=a02.y; af[pb][mi][3]=a13.y;
        }
        #pragma unroll
        for (int ni=0;ni<4;ni++){
            int r=wn*32+ni*8+gid;
            uint2 b01 = *(const uint2*)&Bb[r*GPAD+kc];
            bf[pb][ni][0]=b01.x; bf[pb][ni][1]=b01.y;
        }
    };

    #pragma unroll 1
    for (int t=0;t<GNT;t++){
        CP_WAIT0();
        __syncthreads();
        if (t+1 < GNT) issue(t+1, (t+1)&1);

        unsigned* Ab = As + (t&1)*GBM*GPAD;
        unsigned* Bb = Bs + (t&1)*GBN*GPAD;
        ldfrag(Ab, Bb, 0, 0);
        #pragma unroll
        for (int kk=0;kk<4;kk++){
            int cur = kk & 1;
            if (kk < 3) ldfrag(Ab, Bb, kk+1, cur^1);
            #pragma unroll
            for (int mi=0;mi<4;mi++)
                #pragma unroll
                for (int ni=0;ni<4;ni++)
                    mma8(acc[mi][ni],
                         af[cur][mi][0],af[cur][mi][1],af[cur][mi][2],af[cur][mi][3],
                         bf[cur][ni][0],bf[cur][ni][1]);
        }
    }

    #pragma unroll
    for (int mi=0;mi<4;mi++){
        #pragma unroll
        for (int ni=0;ni<4;ni++){
            int row = m0 + wm*64 + mi*16 + gid;
            int col = n0 + wn*32 + ni*8 + 2*tig;
            float bv0 = bias[col], bv1 = bias[col+1];
            float y0 = acc[mi][ni][0]+bv0, y1 = acc[mi][ni][1]+bv1;
            float y2 = acc[mi][ni][2]+bv0, y3 = acc[mi][ni][3]+bv1;
            if (MODE==3){
                *(float2*)&dst[(size_t)row*DM + col]     = make_float2(y0,y1);
                *(float2*)&dst[(size_t)(row+8)*DM + col] = make_float2(y2,y3);
            } else {
                float r0f = __uint_as_float(f2tf(y0)), r1f = __uint_as_float(f2tf(y1));
                float r2f = __uint_as_float(f2tf(y2)), r3f = __uint_as_float(f2tf(y3));
                int hh = col >> 6, dk = col & 63;
                int b1_ = row >> 11, s1 = row & (SEQ-1);
                int r2 = row + 8;
                int b2_ = r2 >> 11, s2 = r2 & (SEQ-1);
                if (MODE==2){
                    // V: write transposed [bh][d][s-interleaved]
                    int sI1 = (s1 & ~7) | ilv8(s1 & 7);
                    int sI2 = (s2 & ~7) | ilv8(s2 & 7);
                    float* pd0 = &dst[(((size_t)b1_*H_ + hh)*DK + dk)*SEQ];
                    float* pd1 = &dst[(((size_t)b1_*H_ + hh)*DK + dk+1)*SEQ];
                    float* pe0 = &dst[(((size_t)b2_*H_ + hh)*DK + dk)*SEQ];
                    float* pe1 = &dst[(((size_t)b2_*H_ + hh)*DK + dk+1)*SEQ];
                    pd0[sI1]=r0f; pd1[sI1]=r1f; pe0[sI2]=r2f; pe1[sI2]=r3f;
                } else {
                    float* p1 = &dst[(((size_t)b1_*H_ + hh)*SEQ + s1)*DK];
                    float* p2 = &dst[(((size_t)b2_*H_ + hh)*SEQ + s2)*DK];
                    if (MODE==1){
                        int g = dk & ~7, o = dk & 7;
                        int c0 = g | ilv8(o), c1 = g | ilv8(o+1);
                        p1[c0]=r0f; p1[c1]=r1f; p2[c0]=r2f; p2[c1]=r3f;
                    } else {
                        *(float2*)&p1[dk] = make_float2(r0f, r1f);
                        *(float2*)&p2[dk] = make_float2(r2f, r3f);
                    }
                }
            }
        }
    }
}

__global__ void __launch_bounds__(256) gemm_qkv_kernel(
    const float* __restrict__ bq, const float* __restrict__ bk, const float* __restrict__ bv)
{
    int m = blockIdx.z;
    if (m==0)      gemm_core<0>(g_cq, g_cwq, bq, g_q);
    else if (m==1) gemm_core<1>(g_ck, g_cwk, bk, g_k);    // K: d-interleaved
    else           gemm_core<2>(g_cv, g_cwv, bv, g_vt);   // V: transposed
}

__global__ void __launch_bounds__(256) gemm_out_kernel(
    const float* __restrict__ bo, float* __restrict__ out)
{
    gemm_core<3>(g_att, g_cwo, bo, out);
}

// ---------------------------------------------------------------------------
// Flash attention (R11 measured-best core): fixed-max softmax + shfl-free PV
// via store-side key permutation; conflict-free LDS; 2 CTAs/SM.
// ---------------------------------------------------------------------------
#define APAD 72

__global__ void __launch_bounds__(256, 2) attn_kernel()
{
    extern __shared__ unsigned sm_[];
    unsigned* KV = sm_;                    // [2 stages][K(64*APAD) V(64*APAD)]
    unsigned* Qf = sm_ + 4*64*APAD;        // [8 warps][8j][32 lanes][4] = 8192
    float* Qstage = (float*)sm_;           // overlay [128][APAD] over stage 0
    float* s_rb = (float*)(Qf + 8192);     // 72

    int tid=threadIdx.x, lane=tid&31, w=tid>>5;
    int gid=lane>>2, tig=lane&3;
    int bh=blockIdx.y, b=bh>>4, h=bh&15;
    int q0=blockIdx.x<<7;

    if (tid < NREL) s_rb[tid] = g_rb[tid];

    const float* kbase  = g_k  + (size_t)bh*SEQ*DK;
    const float* vtbase = g_vt + (size_t)bh*DK*SEQ;

    // stage Q, repack per-warp fragments into Qf[j][lane][4] (LDS.128 reload)
    {
        const float* qp = g_q + ((size_t)bh*SEQ + q0)*DK;
        #pragma unroll
        for (int i=0;i<8;i++){
            int idx=tid+i*256, r=idx>>4, c=(idx&15)*4;
            cp16(&Qstage[r*APAD+c], qp + (size_t)r*DK + c);
        }
        CP_COMMIT();
        CP_WAIT0();
        __syncthreads();
        int r0 = w*16 + gid;
        unsigned* Qu = (unsigned*)Qstage;
        unsigned* qfw = Qf + w*1024;
        #pragma unroll
        for (int j=0;j<8;j++){
            qfw[j*128 + lane*4 + 0] = Qu[r0*APAD + 8*j+tig];
            qfw[j*128 + lane*4 + 1] = Qu[(r0+8)*APAD + 8*j+tig];
            qfw[j*128 + lane*4 + 2] = Qu[r0*APAD + 8*j+tig+4];
            qfw[j*128 + lane*4 + 3] = Qu[(r0+8)*APAD + 8*j+tig+4];
        }
        __syncthreads();   // all warps done reading Qstage
    }
    int r0 = w*16 + gid;

    auto issue_kv = [&](int kt, int st){
        const float* kp = kbase  + (size_t)(kt<<6)*DK;   // K rows = keys (d interleaved)
        const float* vp = vtbase + (kt<<6);              // Vt rows = d (s interleaved)
        unsigned* Kst = KV + st*2*64*APAD;
        unsigned* Vst = Kst + 64*APAD;
        #pragma unroll
        for (int i=0;i<4;i++){
            int idx=tid+i*256, r=idx>>4, c=(idx&15)*4;
            int rs = (r & ~7) | ilv8(r & 7);             // key row r -> slot ilv8
            cp16(&Kst[rs*APAD+c], kp + (size_t)r*DK + c);
            cp16(&Vst[r*APAD+c],  vp + (size_t)r*SEQ + c);
        }
        CP_COMMIT();
    };
    issue_kv(0, 0);

    float oacc[8][4]={};
    float l0=0.f, l1=0.f;        // per-lane partial sums; reduced once at end
    int qg0 = q0 + r0;
    const unsigned char* mrow0 = g_m8 + (size_t)(b*SEQ + qg0)*SEQ;
    const unsigned char* mrow1 = mrow0 + (size_t)8*SEQ;
    float rb_lo = s_rb[0];   // rel <= -32 (FIXMAX folded in)
    float rb_hi = s_rb[64];  // rel >= 32
    const unsigned* qfw = Qf + w*1024 + lane*4;

    #pragma unroll 1
    for (int kt=0; kt<SEQ/64; kt++){
        int k0 = kt<<6;
        CP_WAIT0();
        __syncthreads();
        if (kt+1 < SEQ/64) issue_kv(kt+1, (kt+1)&1);

        unsigned* Kst = KV + (kt&1)*2*64*APAD;
        unsigned* Vst = Kst + 64*APAD;

        // S = Q @ K^T : conflict-free loads; slots hold permuted keys, so
        // acc regs hold keys (tig, tig+4) = PV A-fragment layout.
        float sacc[8][4]={};
        #pragma unroll
        for (int j=0;j<8;j++){
            uint4 qa = *(const uint4*)&qfw[j*128];
            #pragma unroll
            for (int nt=0;nt<8;nt++){
                uint2 kk2 = *(const uint2*)&Kst[(nt*8+gid)*APAD + 8*j + 2*tig];
                mma8(sacc[nt], qa.x,qa.y,qa.z,qa.w, kk2.x,kk2.y);
            }
        }

        // scale + bias(-FIXMAX) + mask (uchar2 = keys tig, tig+4), direct exp2
        // reg map: [0]=(q=qg0,key=ca) [1]=(qg0,cb=ca+4) [2]=(qg0+8,ca) [3]=(qg0+8,cb)
        int dlo = qg0 - (k0+63);
        int dhi = qg0 + 15 - k0;
        if (dlo >= 32 || dhi <= -32) {
            float bc = (dlo >= 32) ? rb_hi : rb_lo;
            #pragma unroll
            for (int nt=0;nt<8;nt++){
                int cp_ = k0 + nt*8 + 2*tig;
                uchar2 m0v = *(const uchar2*)&mrow0[cp_];
                uchar2 m1v = *(const uchar2*)&mrow1[cp_];
                sacc[nt][0] = (m0v.x==0) ? -3e9f : fmaf(sacc[nt][0],SCALE_L2,bc);
                sacc[nt][1] = (m0v.y==0) ? -3e9f : fmaf(sacc[nt][1],SCALE_L2,bc);
                sacc[nt][2] = (m1v.x==0) ? -3e9f : fmaf(sacc[nt][2],SCALE_L2,bc);
                sacc[nt][3] = (m1v.y==0) ? -3e9f : fmaf(sacc[nt][3],SCALE_L2,bc);
            }
        } else {
            #pragma unroll
            for (int nt=0;nt<8;nt++){
                int cp_ = k0 + nt*8 + 2*tig;
                uchar2 m0v = *(const uchar2*)&mrow0[cp_];
                uchar2 m1v = *(const uchar2*)&mrow1[cp_];
                int ca = k0 + nt*8 + tig;
                int raa = qg0 - ca;
                float b00=s_rb[min(max(raa  ,-32),32)+32];
                float b01=s_rb[min(max(raa-4,-32),32)+32];
                float b10=s_rb[min(max(raa+8,-32),32)+32];
                float b11=s_rb[min(max(raa+4,-32),32)+32];
                sacc[nt][0] = (m0v.x==0) ? -3e9f : fmaf(sacc[nt][0],SCALE_L2,b00);
                sacc[nt][1] = (m0v.y==0) ? -3e9f : fmaf(sacc[nt][1],SCALE_L2,b01);
                sacc[nt][2] = (m1v.x==0) ? -3e9f : fmaf(sacc[nt][2],SCALE_L2,b10);
                sacc[nt][3] = (m1v.y==0) ? -3e9f : fmaf(sacc[nt][3],SCALE_L2,b11);
            }
        }
        unsigned (*pu)[4] = (unsigned(*)[4])sacc;
        #pragma unroll
        for (int nt=0;nt<8;nt++){
            float p0=fexp2(sacc[nt][0]);
            float p1=fexp2(sacc[nt][1]);
            float p2=fexp2(sacc[nt][2]);
            float p3=fexp2(sacc[nt][3]);
            l0 += p0+p1; l1 += p2+p3;
            pu[nt][0]=f2tf(p0); pu[nt][1]=f2tf(p1); pu[nt][2]=f2tf(p2); pu[nt][3]=f2tf(p3);
        }

        // O += P @ V : A-frag = renamed S regs (pu[j][0],pu[j][2],pu[j][1],pu[j][3])
        #pragma unroll
        for (int j=0;j<8;j++){
            unsigned a0=pu[j][0], a1=pu[j][2], a2=pu[j][1], a3=pu[j][3];
            #pragma unroll
            for (int nt=0;nt<8;nt++){
                uint2 vv2 = *(const uint2*)&Vst[(nt*8+gid)*APAD + 8*j + 2*tig];
                mma8(oacc[nt], a0,a1,a2,a3, vv2.x,vv2.y);
            }
        }
    }

    // one final row-sum reduce (4-lane groups), then normalize + write
    l0 += __shfl_xor_sync(0xffffffffu,l0,1);
    l0 += __shfl_xor_sync(0xffffffffu,l0,2);
    l1 += __shfl_xor_sync(0xffffffffu,l1,1);
    l1 += __shfl_xor_sync(0xffffffffu,l1,2);
    float il0=1.f/l0, il1=1.f/l1;
    float* op = g_att + ((size_t)b*SEQ + qg0)*DM + h*64;
    #pragma unroll
    for (int nt=0;nt<8;nt++){
        int d = nt*8 + 2*tig;
        int g = d & ~7, o = d & 7;
        int c0 = g | ilv8(o), c1 = g | ilv8(o+1);
        op[c0] = __uint_as_float(f2tf(oacc[nt][0]*il0));
        op[c1] = __uint_as_float(f2tf(oacc[nt][1]*il0));
        op[(size_t)8*DM + c0] = __uint_as_float(f2tf(oacc[nt][2]*il1));
        op[(size_t)8*DM + c1] = __uint_as_float(f2tf(oacc[nt][3]*il1));
    }
}

// ---------------------------------------------------------------------------
extern "C" void kernel_launch(void* const* d_in, const int* in_sizes, int n_in,
                              void* d_out, int out_size)
{
    const float* query = (const float*)d_in[0];
    const float* key   = (const float*)d_in[1];
    const float* value = (const float*)d_in[2];
    const int*   mask  = (const int*)  d_in[3];
    const float* Wq    = (const float*)d_in[4];
    const float* bq    = (const float*)d_in[5];
    const float* Wk    = (const float*)d_in[6];
    const float* bk    = (const float*)d_in[7];
    const float* Wv    = (const float*)d_in[8];
    const float* bv    = (const float*)d_in[9];
    const float* Wo    = (const float*)d_in[10];
    const float* bo    = (const float*)d_in[11];
    const float* rel   = (const float*)d_in[12];
    float* out = (float*)d_out;

    size_t gsmem = (size_t)(2*GBM*GPAD + 2*GBN*GPAD) * 4;       // 81920 B
    size_t asmem = (size_t)(4*64*APAD + 8192 + 72) * 4;         // 106784 B
    cudaFuncSetAttribute(gemm_qkv_kernel, cudaFuncAttributeMaxDynamicSharedMemorySize, (int)gsmem);
    cudaFuncSetAttribute(gemm_out_kernel, cudaFuncAttributeMaxDynamicSharedMemorySize, (int)gsmem);
    cudaFuncSetAttribute(attn_kernel, cudaFuncAttributeMaxDynamicSharedMemorySize, (int)asmem);

    relbias_kernel<<<1, 128>>>(rel);
    cvt_prepass<<<dim3(1024,1,7), 256>>>(query, key, value, Wq, Wk, Wv, Wo);
    mask_prepass<<<2048, 256>>>(mask);

    dim3 pg(DM/GBN, NROW/GBM, 3);   // (8, 32, 3)
    gemm_qkv_kernel<<<pg, 256, gsmem>>>(bq, bk, bv);

    attn_kernel<<<dim3(SEQ/128, BATCH*H_), 256, asmem>>>();

    gemm_out_kernel<<<dim3(DM/GBN, NROW/GBM), 256, gsmem>>>(bo, out);
}

// round 17
// speedup vs baseline: 1.1282x; 1.0466x over previous
#include <cuda_runtime.h>

#define H_    16
#define DM    1024
#define DK    64
#define BATCH 2
#define SEQ   2048
#define NROW  (BATCH*SEQ)   // 4096
#define NREL  65
#define LOG2E 1.4426950408889634f
#define SCALE_L2 (0.125f*LOG2E)
#define FIXMAX 16.0f        // fixed softmax shift (log2 domain)

// Scratch (device globals: allocation-free scratch per harness rules)
__device__ float g_q[(size_t)BATCH*H_*SEQ*DK];     // natural [bh][s][d]
__device__ float g_k[(size_t)BATCH*H_*SEQ*DK];     // d-axis pair-interleaved
__device__ float g_vt[(size_t)BATCH*H_*DK*SEQ];    // [bh][d][s], s pair-interleaved
__device__ float g_att[(size_t)NROW*DM];           // d-axis pair-interleaved
__device__ float g_rb[NREL];                       // LOG2E*bias - FIXMAX
__device__ unsigned char g_m8[(size_t)BATCH*SEQ*SEQ];  // mask, k pair-interleaved bytes
// tf32-pre-rounded copies, k-axis pair-interleaved for LDS.64 fragments
__device__ float g_cq[(size_t)NROW*DM];
__device__ float g_ck[(size_t)NROW*DM];
__device__ float g_cv[(size_t)NROW*DM];
__device__ float g_cwq[(size_t)DM*DM];
__device__ float g_cwk[(size_t)DM*DM];
__device__ float g_cwv[(size_t)DM*DM];
__device__ float g_cwo[(size_t)DM*DM];

// pair-interleave within 8-groups: true offset o stored at pos 2*(o&3)+(o>>2);
// LDS.64 at pos 2t then yields true (t, t+4) = one mma fragment pair.
__device__ __forceinline__ int ilv8(int o){ return ((o&3)<<1) | (o>>2); }

// ---------------------------------------------------------------------------
// helpers
// ---------------------------------------------------------------------------
__device__ __forceinline__ unsigned f2tf(float x){
    unsigned r; asm("cvt.rna.tf32.f32 %0, %1;" : "=r"(r) : "f"(x)); return r;
}
__device__ __forceinline__ void mma8(float d[4],
    unsigned a0,unsigned a1,unsigned a2,unsigned a3, unsigned b0,unsigned b1){
    asm volatile("mma.sync.aligned.m16n8k8.row.col.f32.tf32.tf32.f32 "
        "{%0,%1,%2,%3}, {%4,%5,%6,%7}, {%8,%9}, {%0,%1,%2,%3};"
        : "+f"(d[0]),"+f"(d[1]),"+f"(d[2]),"+f"(d[3])
        : "r"(a0),"r"(a1),"r"(a2),"r"(a3),"r"(b0),"r"(b1));
}
__device__ __forceinline__ void cp16(void* sp, const void* gp){
    unsigned s = (unsigned)__cvta_generic_to_shared(sp);
    asm volatile("cp.async.ca.shared.global [%0], [%1], 16;" :: "r"(s), "l"(gp));
}
#define CP_COMMIT() asm volatile("cp.async.commit_group;")
#define CP_WAIT0()  asm volatile("cp.async.wait_group 0;")

// exp2 on the fma/alu pipes (MUFU is only 0.5/cyc/SM on sm_103a)
__device__ __forceinline__ float fexp2(float y){
    y = fmaxf(y, -126.f);
    float z = y + 12582912.f;
    int   e = __float_as_int(z) - 0x4B400000;
    float f = y - (z - 12582912.f);
    float p =             1.3333558146e-3f;
    p = fmaf(p, f, 9.6181291918e-3f);
    p = fmaf(p, f, 5.5504108664e-2f);
    p = fmaf(p, f, 2.4022650695e-1f);
    p = fmaf(p, f, 6.9314718056e-1f);
    p = fmaf(p, f, 1.0f);
    return __int_as_float(__float_as_int(p) + (e << 23));
}

// ---------------------------------------------------------------------------
// prepass: tf32-round + k-axis pair-interleave (z selects array)
// ---------------------------------------------------------------------------
__global__ void cvt_prepass(const float* __restrict__ q, const float* __restrict__ k,
                            const float* __restrict__ v, const float* __restrict__ wq,
                            const float* __restrict__ wk, const float* __restrict__ wv,
                            const float* __restrict__ wo)
{
    int z = blockIdx.z;
    const float4* src; float* dst; int n4;
    switch (z) {
        case 0: src=(const float4*)q;  dst=g_cq;  n4=NROW*DM/4; break;
        case 1: src=(const float4*)k;  dst=g_ck;  n4=NROW*DM/4; break;
        case 2: src=(const float4*)v;  dst=g_cv;  n4=NROW*DM/4; break;
        case 3: src=(const float4*)wq; dst=g_cwq; n4=DM*DM/4;   break;
        case 4: src=(const float4*)wk; dst=g_cwk; n4=DM*DM/4;   break;
        case 5: src=(const float4*)wv; dst=g_cwv; n4=DM*DM/4;   break;
        default:src=(const float4*)wo; dst=g_cwo; n4=DM*DM/4;   break;
    }
    for (int i = blockIdx.x*blockDim.x + threadIdx.x; i < n4; i += gridDim.x*blockDim.x){
        float4 a = src[i];
        int par  = (i & 1);                       // true offsets 0-3 (even) / 4-7 (odd)
        size_t fb = ((size_t)i << 2) & ~7ull;     // 8-aligned flat base
        dst[fb + par + 0] = __uint_as_float(f2tf(a.x));
        dst[fb + par + 2] = __uint_as_float(f2tf(a.y));
        dst[fb + par + 4] = __uint_as_float(f2tf(a.z));
        dst[fb + par + 6] = __uint_as_float(f2tf(a.w));
    }
}

// ---------------------------------------------------------------------------
// mask prepass: int32 -> uint8, k-axis pair-interleaved (uchar2 = keys t,t+4)
// ---------------------------------------------------------------------------
__global__ void mask_prepass(const int* __restrict__ mask)
{
    size_t n4 = (size_t)BATCH*SEQ*SEQ/4;
    for (size_t i = blockIdx.x*blockDim.x + threadIdx.x; i < n4;
         i += (size_t)gridDim.x*blockDim.x){
        int4 m = ((const int4*)mask)[i];
        size_t fb = (i << 2) & ~7ull;
        int par = (int)(i & 1);
        g_m8[fb + par + 0] = (unsigned char)(m.x != 0);
        g_m8[fb + par + 2] = (unsigned char)(m.y != 0);
        g_m8[fb + par + 4] = (unsigned char)(m.z != 0);
        g_m8[fb + par + 6] = (unsigned char)(m.w != 0);
    }
}

// ---------------------------------------------------------------------------
// rel bias (log2 domain, fixed softmax shift folded in)
// ---------------------------------------------------------------------------
__global__ void relbias_kernel(const float* __restrict__ rel_emb) {
    int i = threadIdx.x;
    if (i < NREL) {
        float s = 0.f;
        #pragma unroll
        for (int d = 0; d < DK; d++) s += rel_emb[i*DK + d];
        g_rb[i] = s * LOG2E - FIXMAX;
    }
}

// ---------------------------------------------------------------------------
// GEMM core (R11 measured-best): BM=128, BN=128, BK=32, 2-stage cp.async,
// 256 threads, warps 2(m)x4(n), warp tile 64x32.
// MODE: 0 = scatter natural (g_q), 1 = scatter d-interleaved (g_k),
//       2 = scatter V-transposed into g_vt, 3 = plain row-major out.
// ---------------------------------------------------------------------------
#define GBM 128
#define GBN 128
#define GBK 32
#define GPAD 40
#define GNT  (DM/GBK)

template<int MODE>
__device__ __forceinline__ void gemm_core(const float* __restrict__ X,
    const float* __restrict__ W, const float* __restrict__ bias,
    float* __restrict__ dst)
{
    extern __shared__ unsigned gsm[];
    unsigned* As = gsm;                    // [2][128][GPAD]
    unsigned* Bs = gsm + 2*GBM*GPAD;       // [2][128][GPAD]

    int tid=threadIdx.x, lane=tid&31, w=tid>>5;
    int gid=lane>>2, tig=lane&3;
    int wm=w>>2, wn=w&3;                   // 2 x 4 warp grid
    int m0=blockIdx.y*GBM, n0=blockIdx.x*GBN;

    int lr=tid>>3, lc=(tid&7)*4;
    const float* xp = X + (size_t)(m0+lr)*DM + lc;
    const float* wp = W + (size_t)(n0+lr)*DM + lc;

    auto issue = [&](int t, int buf){
        int k0 = t*GBK;
        #pragma unroll
        for (int i=0;i<4;i++)
            cp16(&As[buf*GBM*GPAD + (lr+32*i)*GPAD + lc], xp + k0 + (size_t)32*i*DM);
        #pragma unroll
        for (int i=0;i<4;i++)
            cp16(&Bs[buf*GBN*GPAD + (lr+32*i)*GPAD + lc], wp + k0 + (size_t)32*i*DM);
        CP_COMMIT();
    };

    issue(0, 0);

    float acc[4][4][4]={};
    #pragma unroll 1
    for (int t=0;t<GNT;t++){
        CP_WAIT0();
        __syncthreads();
        if (t+1 < GNT) issue(t+1, (t+1)&1);

        unsigned* Ab = As + (t&1)*GBM*GPAD;
        unsigned* Bb = Bs + (t&1)*GBN*GPAD;
        #pragma unroll
        for (int kk=0;kk<4;kk++){
            int kc=kk*8 + 2*tig;
            unsigned af[4][4], bf[4][2];
            #pragma unroll
            for (int mi=0;mi<4;mi++){
                int r=wm*64+mi*16+gid;
                uint2 a02 = *(const uint2*)&Ab[r*GPAD+kc];
                uint2 a13 = *(const uint2*)&Ab[(r+8)*GPAD+kc];
                af[mi][0]=a02.x; af[mi][1]=a13.x; af[mi][2]=a02.y; af[mi][3]=a13.y;
            }
            #pragma unroll
            for (int ni=0;ni<4;ni++){
                int r=wn*32+ni*8+gid;
                uint2 b01 = *(const uint2*)&Bb[r*GPAD+kc];
                bf[ni][0]=b01.x; bf[ni][1]=b01.y;
            }
            #pragma unroll
            for (int mi=0;mi<4;mi++)
                #pragma unroll
                for (int ni=0;ni<4;ni++)
                    mma8(acc[mi][ni], af[mi][0],af[mi][1],af[mi][2],af[mi][3],
                         bf[ni][0],bf[ni][1]);
        }
    }

    #pragma unroll
    for (int mi=0;mi<4;mi++){
        #pragma unroll
        for (int ni=0;ni<4;ni++){
            int row = m0 + wm*64 + mi*16 + gid;
            int col = n0 + wn*32 + ni*8 + 2*tig;
            float bv0 = bias[col], bv1 = bias[col+1];
            float y0 = acc[mi][ni][0]+bv0, y1 = acc[mi][ni][1]+bv1;
            float y2 = acc[mi][ni][2]+bv0, y3 = acc[mi][ni][3]+bv1;
            if (MODE==3){
                *(float2*)&dst[(size_t)row*DM + col]     = make_float2(y0,y1);
                *(float2*)&dst[(size_t)(row+8)*DM + col] = make_float2(y2,y3);
            } else {
                float r0f = __uint_as_float(f2tf(y0)), r1f = __uint_as_float(f2tf(y1));
                float r2f = __uint_as_float(f2tf(y2)), r3f = __uint_as_float(f2tf(y3));
                int hh = col >> 6, dk = col & 63;
                int b1_ = row >> 11, s1 = row & (SEQ-1);
                int r2 = row + 8;
                int b2_ = r2 >> 11, s2 = r2 & (SEQ-1);
                if (MODE==2){
                    int sI1 = (s1 & ~7) | ilv8(s1 & 7);
                    int sI2 = (s2 & ~7) | ilv8(s2 & 7);
                    float* pd0 = &dst[(((size_t)b1_*H_ + hh)*DK + dk)*SEQ];
                    float* pd1 = &dst[(((size_t)b1_*H_ + hh)*DK + dk+1)*SEQ];
                    float* pe0 = &dst[(((size_t)b2_*H_ + hh)*DK + dk)*SEQ];
                    float* pe1 = &dst[(((size_t)b2_*H_ + hh)*DK + dk+1)*SEQ];
                    pd0[sI1]=r0f; pd1[sI1]=r1f; pe0[sI2]=r2f; pe1[sI2]=r3f;
                } else {
                    float* p1 = &dst[(((size_t)b1_*H_ + hh)*SEQ + s1)*DK];
                    float* p2 = &dst[(((size_t)b2_*H_ + hh)*SEQ + s2)*DK];
                    if (MODE==1){
                        int g = dk & ~7, o = dk & 7;
                        int c0 = g | ilv8(o), c1 = g | ilv8(o+1);
                        p1[c0]=r0f; p1[c1]=r1f; p2[c0]=r2f; p2[c1]=r3f;
                    } else {
                        *(float2*)&p1[dk] = make_float2(r0f, r1f);
                        *(float2*)&p2[dk] = make_float2(r2f, r3f);
                    }
                }
            }
        }
    }
}

__global__ void __launch_bounds__(256) gemm_qkv_kernel(
    const float* __restrict__ bq, const float* __restrict__ bk, const float* __restrict__ bv)
{
    int m = blockIdx.z;
    if (m==0)      gemm_core<0>(g_cq, g_cwq, bq, g_q);
    else if (m==1) gemm_core<1>(g_ck, g_cwk, bk, g_k);    // K: d-interleaved
    else           gemm_core<2>(g_cv, g_cwv, bv, g_vt);   // V: transposed
}

__global__ void __launch_bounds__(256) gemm_out_kernel(
    const float* __restrict__ bo, float* __restrict__ out)
{
    gemm_core<3>(g_att, g_cwo, bo, out);
}

// ---------------------------------------------------------------------------
// Flash attention, split-K warp tiling: 8 warps = 4 q-groups x 2 k-halves,
// each warp 32q x 32k -> K/V fragments reused across 2 m-frags (33% fewer
// smem wavefronts). Fixed-max softmax + shfl-free PV (store-side permute).
// End-of-kernel smem combine of the two k-half partials (O and l).
// ---------------------------------------------------------------------------
#define APAD 72
#define OST  66

__global__ void __launch_bounds__(256, 2) attn_kernel()
{
    extern __shared__ unsigned sm_[];
    unsigned* KV = sm_;                    // [2 stages][K(64*APAD) V(64*APAD)]
    unsigned* Qf = sm_ + 4*64*APAD;        // [8 m-groups][8j][32 lanes][4] = 8192
    float* Qstage = (float*)sm_;           // overlay [128][APAD] over stage 0
    float* s_rb = (float*)(Qf + 8192);     // 72
    float* Lb   = s_rb + 72;               // 128 (k-half-1 partial l)
    float* Ob   = (float*)sm_;             // overlay KV after final sync [128][OST]

    int tid=threadIdx.x, lane=tid&31, w=tid>>5;
    int gid=lane>>2, tig=lane&3;
    int wq=w>>1, wk=w&1;                   // 4 q-groups x 2 k-halves
    int bh=blockIdx.y, b=bh>>4, h=bh&15;
    int q0=blockIdx.x<<7;

    if (tid < NREL) s_rb[tid] = g_rb[tid];

    const float* kbase  = g_k  + (size_t)bh*SEQ*DK;
    const float* vtbase = g_vt + (size_t)bh*DK*SEQ;

    // stage Q, repack fragments into Qf by 16-row m-group (warp w handles group w)
    {
        const float* qp = g_q + ((size_t)bh*SEQ + q0)*DK;
        #pragma unroll
        for (int i=0;i<8;i++){
            int idx=tid+i*256, r=idx>>4, c=(idx&15)*4;
            cp16(&Qstage[r*APAD+c], qp + (size_t)r*DK + c);
        }
        CP_COMMIT();
        CP_WAIT0();
        __syncthreads();
        int r0 = w*16 + gid;
        unsigned* Qu = (unsigned*)Qstage;
        unsigned* qfw = Qf + w*1024;
        #pragma unroll
        for (int j=0;j<8;j++){
            qfw[j*128 + lane*4 + 0] = Qu[r0*APAD + 8*j+tig];
            qfw[j*128 + lane*4 + 1] = Qu[(r0+8)*APAD + 8*j+tig];
            qfw[j*128 + lane*4 + 2] = Qu[r0*APAD + 8*j+tig+4];
            qfw[j*128 + lane*4 + 3] = Qu[(r0+8)*APAD + 8*j+tig+4];
        }
        __syncthreads();   // all warps done reading Qstage
    }

    auto issue_kv = [&](int kt, int st){
        const float* kp = kbase  + (size_t)(kt<<6)*DK;
        const float* vp = vtbase + (kt<<6);
        unsigned* Kst = KV + st*2*64*APAD;
        unsigned* Vst = Kst + 64*APAD;
        #pragma unroll
        for (int i=0;i<4;i++){
            int idx=tid+i*256, r=idx>>4, c=(idx&15)*4;
            int rs = (r & ~7) | ilv8(r & 7);             // key row r -> slot ilv8
            cp16(&Kst[rs*APAD+c], kp + (size_t)r*DK + c);
            cp16(&Vst[r*APAD+c],  vp + (size_t)r*SEQ + c);
        }
        CP_COMMIT();
    };
    issue_kv(0, 0);

    float oacc[2][8][4]={};
    float lacc[4]={0.f,0.f,0.f,0.f};
    int qr0 = q0 + wq*32 + gid;            // mi=0 row base (rows qr0, +8, +16, +24)
    const unsigned char* mr0 = g_m8 + (size_t)(b*SEQ + qr0)*SEQ;
    float rb_lo = s_rb[0];
    float rb_hi = s_rb[64];
    const unsigned* qf0 = Qf + (wq*2+0)*1024 + lane*4;
    const unsigned* qf1 = Qf + (wq*2+1)*1024 + lane*4;
    int kwo = wk*32;                       // this warp's key offset within tile

    #pragma unroll 1
    for (int kt=0; kt<SEQ/64; kt++){
        int k0 = kt<<6;
        CP_WAIT0();
        __syncthreads();
        if (kt+1 < SEQ/64) issue_kv(kt+1, (kt+1)&1);

        unsigned* Kst = KV + (kt&1)*2*64*APAD;
        unsigned* Vst = Kst + 64*APAD;

        // S = Q @ K^T : each K fragment feeds BOTH m-frags (mi=0,1)
        float sacc[2][4][4]={};
        #pragma unroll
        for (int j=0;j<8;j++){
            uint4 qa0 = *(const uint4*)&qf0[j*128];
            uint4 qa1 = *(const uint4*)&qf1[j*128];
            #pragma unroll
            for (int nt=0;nt<4;nt++){
                uint2 kk2 = *(const uint2*)&Kst[(kwo+nt*8+gid)*APAD + 8*j + 2*tig];
                mma8(sacc[0][nt], qa0.x,qa0.y,qa0.z,qa0.w, kk2.x,kk2.y);
                mma8(sacc[1][nt], qa1.x,qa1.y,qa1.z,qa1.w, kk2.x,kk2.y);
            }
        }

        // scale + bias(-FIXMAX) + mask + exp2; keys are (tig, tig+4) per frag
        int kb = k0 + kwo;
        int dlo = (q0 + wq*32) - (kb + 31);
        int dhi = (q0 + wq*32 + 31) - kb;
        unsigned (*pu)[4][4] = (unsigned(*)[4][4])sacc;
        if (dlo >= 32 || dhi <= -32) {
            float bc = (dlo >= 32) ? rb_hi : rb_lo;
            #pragma unroll
            for (int mi=0;mi<2;mi++){
                const unsigned char* mra = mr0 + (size_t)(mi*16)*SEQ;
                const unsigned char* mrb = mra + (size_t)8*SEQ;
                #pragma unroll
                for (int nt=0;nt<4;nt++){
                    int cp_ = kb + nt*8 + 2*tig;
                    uchar2 m0v = *(const uchar2*)&mra[cp_];
                    uchar2 m1v = *(const uchar2*)&mrb[cp_];
                    float s0 = (m0v.x==0) ? -3e9f : fmaf(sacc[mi][nt][0],SCALE_L2,bc);
                    float s1 = (m0v.y==0) ? -3e9f : fmaf(sacc[mi][nt][1],SCALE_L2,bc);
                    float s2 = (m1v.x==0) ? -3e9f : fmaf(sacc[mi][nt][2],SCALE_L2,bc);
                    float s3 = (m1v.y==0) ? -3e9f : fmaf(sacc[mi][nt][3],SCALE_L2,bc);
                    float p0=fexp2(s0), p1=fexp2(s1), p2=fexp2(s2), p3=fexp2(s3);
                    lacc[mi*2]   += p0+p1;
                    lacc[mi*2+1] += p2+p3;
                    pu[mi][nt][0]=f2tf(p0); pu[mi][nt][1]=f2tf(p1);
                    pu[mi][nt][2]=f2tf(p2); pu[mi][nt][3]=f2tf(p3);
                }
            }
        } else {
            #pragma unroll
            for (int mi=0;mi<2;mi++){
                const unsigned char* mra = mr0 + (size_t)(mi*16)*SEQ;
                const unsigned char* mrb = mra + (size_t)8*SEQ;
                #pragma unroll
                for (int nt=0;nt<4;nt++){
                    int cp_ = kb + nt*8 + 2*tig;
                    uchar2 m0v = *(const uchar2*)&mra[cp_];
                    uchar2 m1v = *(const uchar2*)&mrb[cp_];
                    int ca = kb + nt*8 + tig;
                    int raa = (qr0 + mi*16) - ca;
                    float b00=s_rb[min(max(raa  ,-32),32)+32];
                    float b01=s_rb[min(max(raa-4,-32),32)+32];
                    float b10=s_rb[min(max(raa+8,-32),32)+32];
                    float b11=s_rb[min(max(raa+4,-32),32)+32];
                    float s0 = (m0v.x==0) ? -3e9f : fmaf(sacc[mi][nt][0],SCALE_L2,b00);
                    float s1 = (m0v.y==0) ? -3e9f : fmaf(sacc[mi][nt][1],SCALE_L2,b01);
                    float s2 = (m1v.x==0) ? -3e9f : fmaf(sacc[mi][nt][2],SCALE_L2,b10);
                    float s3 = (m1v.y==0) ? -3e9f : fmaf(sacc[mi][nt][3],SCALE_L2,b11);
                    float p0=fexp2(s0), p1=fexp2(s1), p2=fexp2(s2), p3=fexp2(s3);
                    lacc[mi*2]   += p0+p1;
                    lacc[mi*2+1] += p2+p3;
                    pu[mi][nt][0]=f2tf(p0); pu[mi][nt][1]=f2tf(p1);
                    pu[mi][nt][2]=f2tf(p2); pu[mi][nt][3]=f2tf(p3);
                }
            }
        }

        // O += P @ V : each V fragment feeds BOTH m-frags; A-frag = renamed pu
        #pragma unroll
        for (int j2=0;j2<4;j2++){
            unsigned a00=pu[0][j2][0], a01=pu[0][j2][2], a02=pu[0][j2][1], a03=pu[0][j2][3];
            unsigned a10=pu[1][j2][0], a11=pu[1][j2][2], a12=pu[1][j2][1], a13=pu[1][j2][3];
            #pragma unroll
            for (int nt=0;nt<8;nt++){
                uint2 vv2 = *(const uint2*)&Vst[(nt*8+gid)*APAD + kwo + j2*8 + 2*tig];
                mma8(oacc[0][nt], a00,a01,a02,a03, vv2.x,vv2.y);
                mma8(oacc[1][nt], a10,a11,a12,a13, vv2.x,vv2.y);
            }
        }
    }

    // reduce l within 4-lane groups (row sums)
    #pragma unroll
    for (int i=0;i<4;i++){
        lacc[i] += __shfl_xor_sync(0xffffffffu, lacc[i], 1);
        lacc[i] += __shfl_xor_sync(0xffffffffu, lacc[i], 2);
    }
    __syncthreads();   // all tiles done; KV smem free -> Ob overlay

    if (wk==1){
        #pragma unroll
        for (int mi=0;mi<2;mi++){
            int r = wq*32 + mi*16 + gid;
            Lb[r]   = lacc[mi*2];
            Lb[r+8] = lacc[mi*2+1];
            #pragma unroll
            for (int nt=0;nt<8;nt++){
                int c = nt*8 + 2*tig;
                *(float2*)&Ob[r*OST + c]     = make_float2(oacc[mi][nt][0], oacc[mi][nt][1]);
                *(float2*)&Ob[(r+8)*OST + c] = make_float2(oacc[mi][nt][2], oacc[mi][nt][3]);
            }
        }
    }
    __syncthreads();
    if (wk==0){
        float* op = g_att + ((size_t)b*SEQ + q0)*DM + h*64;
        #pragma unroll
        for (int mi=0;mi<2;mi++){
            int r = wq*32 + mi*16 + gid;
            float il0 = 1.f/(lacc[mi*2]   + Lb[r]);
            float il1 = 1.f/(lacc[mi*2+1] + Lb[r+8]);
            #pragma unroll
            for (int nt=0;nt<8;nt++){
                int c = nt*8 + 2*tig;
                float o0 = (oacc[mi][nt][0] + Ob[r*OST + c])       * il0;
                float o1 = (oacc[mi][nt][1] + Ob[r*OST + c + 1])   * il0;
                float o2 = (oacc[mi][nt][2] + Ob[(r+8)*OST + c])   * il1;
                float o3 = (oacc[mi][nt][3] + Ob[(r+8)*OST + c+1]) * il1;
                int g = c & ~7, o_ = c & 7;
                int c0 = g | ilv8(o_), c1 = g | ilv8(o_+1);
                op[(size_t)r*DM + c0]     = __uint_as_float(f2tf(o0));
                op[(size_t)r*DM + c1]     = __uint_as_float(f2tf(o1));
                op[(size_t)(r+8)*DM + c0] = __uint_as_float(f2tf(o2));
                op[(size_t)(r+8)*DM + c1] = __uint_as_float(f2tf(o3));
            }
        }
    }
}

// ---------------------------------------------------------------------------
extern "C" void kernel_launch(void* const* d_in, const int* in_sizes, int n_in,
                              void* d_out, int out_size)
{
    const float* query = (const float*)d_in[0];
    const float* key   = (const float*)d_in[1];
    const float* value = (const float*)d_in[2];
    const int*   mask  = (const int*)  d_in[3];
    const float* Wq    = (const float*)d_in[4];
    const float* bq    = (const float*)d_in[5];
    const float* Wk    = (const float*)d_in[6];
    const float* bk    = (const float*)d_in[7];
    const float* Wv    = (const float*)d_in[8];
    const float* bv    = (const float*)d_in[9];
    const float* Wo    = (const float*)d_in[10];
    const float* bo    = (const float*)d_in[11];
    const float* rel   = (const float*)d_in[12];
    float* out = (float*)d_out;

    size_t gsmem = (size_t)(2*GBM*GPAD + 2*GBN*GPAD) * 4;        // 81920 B
    size_t asmem = (size_t)(4*64*APAD + 8192 + 72 + 128) * 4;    // 107296 B
    cudaFuncSetAttribute(gemm_qkv_kernel, cudaFuncAttributeMaxDynamicSharedMemorySize, (int)gsmem);
    cudaFuncSetAttribute(gemm_out_kernel, cudaFuncAttributeMaxDynamicSharedMemorySize, (int)gsmem);
    cudaFuncSetAttribute(attn_kernel, cudaFuncAttributeMaxDynamicSharedMemorySize, (int)asmem);

    relbias_kernel<<<1, 128>>>(rel);
    cvt_prepass<<<dim3(1024,1,7), 256>>>(query, key, value, Wq, Wk, Wv, Wo);
    mask_prepass<<<2048, 256>>>(mask);

    dim3 pg(DM/GBN, NROW/GBM, 3);   // (8, 32, 3)
    gemm_qkv_kernel<<<pg, 256, gsmem>>>(bq, bk, bv);

    attn_kernel<<<dim3(SEQ/128, BATCH*H_), 256, asmem>>>();

    gemm_out_kernel<<<dim3(DM/GBN, NROW/GBM), 256, gsmem>>>(bo, out);
}